// round 1
// baseline (speedup 1.0000x reference)
#include <cuda_runtime.h>
#include <math.h>

// ---------------- problem constants ----------------
#define BATCH   32
#define IMG_H   56
#define IMG_W   56
#define CH      256
#define WS      7
#define SHIFT_  3
#define HEADS   8
#define HD      32
#define HIDDEN  1024
#define NTOK    49          // WS*WS
#define NWIN    64          // (56/7)^2 windows per image
#define T_TOK   (BATCH*IMG_H*IMG_W)   // 100352 tokens

// ---------------- scratch (no allocations allowed) ----------------
__device__ float g_xw [(size_t)T_TOK * CH];       // LN1-partitioned input; reused for attn output
__device__ float g_qkv[(size_t)T_TOK * 3 * CH];
__device__ float g_y  [(size_t)T_TOK * CH];       // residual after attention branch
__device__ float g_z  [(size_t)T_TOK * CH];       // LN2 output
__device__ float g_m1 [(size_t)T_TOK * HIDDEN];   // fc1/gelu output

// window-token-row -> original-token index (same map for partition and reverse)
__device__ __forceinline__ int map_token(int r) {
    int w = r / NTOK, n = r - w * NTOK;
    int b = w >> 6, widx = w & 63;
    int wh = widx >> 3, ww = widx & 7;
    int i = n / WS, j = n - i * WS;
    int h = wh * WS + i + SHIFT_;  if (h >= IMG_H) h -= IMG_H;
    int v = ww * WS + j + SHIFT_;  if (v >= IMG_W) v -= IMG_W;
    return (b * IMG_H + h) * IMG_W + v;
}

// ---------------- LayerNorm (one warp per token row of 256) ----------------
// MODE 0: read x at map_token(row), write g_xw[row]   (LN1 + roll + partition)
// MODE 1: identity mapping                             (LN2)
template<int MODE>
__global__ void __launch_bounds__(256) ln_kernel(const float* __restrict__ in,
                                                 const float* __restrict__ gam,
                                                 const float* __restrict__ bet,
                                                 float* __restrict__ out) {
    int warp = (blockIdx.x * blockDim.x + threadIdx.x) >> 5;
    int lane = threadIdx.x & 31;
    if (warp >= T_TOK) return;
    int src = (MODE == 0) ? map_token(warp) : warp;

    const float4* row = (const float4*)(in + (size_t)src * CH);
    float4 a = row[lane];
    float4 b = row[lane + 32];

    float s = a.x + a.y + a.z + a.w + b.x + b.y + b.z + b.w;
    #pragma unroll
    for (int o = 16; o; o >>= 1) s += __shfl_xor_sync(0xffffffffu, s, o);
    float mu = s * (1.0f / CH);

    float vs = 0.f, d;
    d = a.x - mu; vs += d * d;  d = a.y - mu; vs += d * d;
    d = a.z - mu; vs += d * d;  d = a.w - mu; vs += d * d;
    d = b.x - mu; vs += d * d;  d = b.y - mu; vs += d * d;
    d = b.z - mu; vs += d * d;  d = b.w - mu; vs += d * d;
    #pragma unroll
    for (int o = 16; o; o >>= 1) vs += __shfl_xor_sync(0xffffffffu, vs, o);
    float inv = rsqrtf(vs * (1.0f / CH) + 1e-5f);

    float4 g0 = ((const float4*)gam)[lane], g1 = ((const float4*)gam)[lane + 32];
    float4 b0 = ((const float4*)bet)[lane], b1 = ((const float4*)bet)[lane + 32];
    float4 o0, o1;
    o0.x = (a.x - mu) * inv * g0.x + b0.x;  o0.y = (a.y - mu) * inv * g0.y + b0.y;
    o0.z = (a.z - mu) * inv * g0.z + b0.z;  o0.w = (a.w - mu) * inv * g0.w + b0.w;
    o1.x = (b.x - mu) * inv * g1.x + b1.x;  o1.y = (b.y - mu) * inv * g1.y + b1.y;
    o1.z = (b.z - mu) * inv * g1.z + b1.z;  o1.w = (b.w - mu) * inv * g1.w + b1.w;

    float4* orow = (float4*)(out + (size_t)warp * CH);
    orow[lane] = o0;
    orow[lane + 32] = o1;
}

// ---------------- fp32 SGEMM 128x128x8, 256 threads, 8x8 microtile ----------------
// C = A(MxK,row) @ B(KxN,row) with epilogue:
//   EPI 0: += bias[col]                                  (qkv)
//   EPI 1: scatter row via map_token, += x + bias        (proj + reverse + shortcut)
//   EPI 2: gelu(acc + bias)  (exact erf)                 (fc1)
//   EPI 3: += extra[row] + bias -> out                   (fc2 + residual)
template<int EPI>
__global__ void __launch_bounds__(256) sgemm(const float* __restrict__ A,
                                             const float* __restrict__ Bw,
                                             const float* __restrict__ bias,
                                             float* __restrict__ Cout,
                                             int Ndim, int Kdim,
                                             const float* __restrict__ extra) {
    __shared__ float As[8][128];
    __shared__ float Bs[8][128];

    const int tid  = threadIdx.x;
    const int brow = blockIdx.y * 128;
    const int bcol = blockIdx.x * 128;

    const int arow  = tid >> 1;
    const int acol  = (tid & 1) << 2;
    const int bro   = tid >> 5;
    const int bco   = (tid & 31) << 2;
    const int tx    = (tid & 15) << 3;
    const int ty    = (tid >> 4) << 3;

    const float* Aptr = A  + (size_t)(brow + arow) * Kdim + acol;
    const float* Bptr = Bw + (size_t)bro * Ndim + bcol + bco;

    float acc[8][8];
    #pragma unroll
    for (int i = 0; i < 8; i++)
        #pragma unroll
        for (int j = 0; j < 8; j++) acc[i][j] = 0.f;

    for (int kt = 0; kt < Kdim; kt += 8) {
        float4 av = *(const float4*)(Aptr + kt);
        float4 bv = *(const float4*)(Bptr + (size_t)kt * Ndim);
        As[acol + 0][arow] = av.x;  As[acol + 1][arow] = av.y;
        As[acol + 2][arow] = av.z;  As[acol + 3][arow] = av.w;
        *(float4*)&Bs[bro][bco] = bv;
        __syncthreads();

        #pragma unroll
        for (int k = 0; k < 8; k++) {
            float4 a0 = *(float4*)&As[k][ty];
            float4 a1 = *(float4*)&As[k][ty + 4];
            float4 c0 = *(float4*)&Bs[k][tx];
            float4 c1 = *(float4*)&Bs[k][tx + 4];
            float ar[8] = {a0.x, a0.y, a0.z, a0.w, a1.x, a1.y, a1.z, a1.w};
            float br[8] = {c0.x, c0.y, c0.z, c0.w, c1.x, c1.y, c1.z, c1.w};
            #pragma unroll
            for (int i = 0; i < 8; i++)
                #pragma unroll
                for (int j = 0; j < 8; j++) acc[i][j] += ar[i] * br[j];
        }
        __syncthreads();
    }

    #pragma unroll
    for (int i = 0; i < 8; i++) {
        int r = brow + ty + i;
        int t = (EPI == 1) ? map_token(r) : r;
        #pragma unroll
        for (int j = 0; j < 8; j++) {
            int col = bcol + tx + j;
            float v = acc[i][j] + bias[col];
            if (EPI == 0) {
                Cout[(size_t)r * Ndim + col] = v;
            } else if (EPI == 1) {
                Cout[(size_t)t * CH + col] = extra[(size_t)t * CH + col] + v;
            } else if (EPI == 2) {
                Cout[(size_t)r * Ndim + col] = 0.5f * v * (1.0f + erff(v * 0.70710678118654752f));
            } else {
                Cout[(size_t)r * CH + col] = extra[(size_t)r * CH + col] + v;
            }
        }
    }
}

// ---------------- attention: one block per (window, head) ----------------
__global__ void __launch_bounds__(128) attn_kernel(const float* __restrict__ qkv,
                                                   const float* __restrict__ rel_bias,
                                                   float* __restrict__ out) {
    const int blk = blockIdx.x;
    const int w   = blk >> 3;
    const int hh  = blk & 7;
    const int tid = threadIdx.x;

    __shared__ float q[NTOK][HD + 1];
    __shared__ float k[NTOK][HD + 1];
    __shared__ float v[NTOK][HD + 1];
    __shared__ float S[NTOK][NTOK + 3];

    const float scale = 0.17677669529663687f;  // 32^-0.5

    for (int idx = tid; idx < NTOK * 8; idx += 128) {
        int n = idx >> 3, c4 = (idx & 7) << 2;
        size_t base = (size_t)(w * NTOK + n) * (3 * CH) + hh * HD + c4;
        float4 qv = *(const float4*)(qkv + base);
        float4 kv = *(const float4*)(qkv + base + CH);
        float4 vv = *(const float4*)(qkv + base + 2 * CH);
        q[n][c4 + 0] = qv.x * scale; q[n][c4 + 1] = qv.y * scale;
        q[n][c4 + 2] = qv.z * scale; q[n][c4 + 3] = qv.w * scale;
        k[n][c4 + 0] = kv.x; k[n][c4 + 1] = kv.y; k[n][c4 + 2] = kv.z; k[n][c4 + 3] = kv.w;
        v[n][c4 + 0] = vv.x; v[n][c4 + 1] = vv.y; v[n][c4 + 2] = vv.z; v[n][c4 + 3] = vv.w;
    }
    __syncthreads();

    const int widx = w & 63;
    const int wh = widx >> 3, ww = widx & 7;

    for (int idx = tid; idx < NTOK * NTOK; idx += 128) {
        int n = idx / NTOK, m = idx - n * NTOK;
        float s = 0.f;
        #pragma unroll
        for (int d = 0; d < HD; d++) s += q[n][d] * k[m][d];
        int in_ = n / WS, jn = n - in_ * WS;
        int im  = m / WS, jm = m - im * WS;
        // relative position bias: idx = (i_m - i_n + 6)*13 + (j_m - j_n + 6)
        s += rel_bias[((im - in_ + 6) * 13 + (jm - jn + 6)) * HEADS + hh];
        // shifted-window mask via region tags
        int hn = wh * WS + in_, wn = ww * WS + jn;
        int hm = wh * WS + im,  wm = ww * WS + jm;
        int tn = (hn < 49 ? 0 : (hn < 53 ? 1 : 2)) * 3 + (wn < 49 ? 0 : (wn < 53 ? 1 : 2));
        int tm = (hm < 49 ? 0 : (hm < 53 ? 1 : 2)) * 3 + (wm < 49 ? 0 : (wm < 53 ? 1 : 2));
        if (tn != tm) s -= 100.0f;
        S[n][m] = s;
    }
    __syncthreads();

    const int warp = tid >> 5, lane = tid & 31;
    for (int n = warp; n < NTOK; n += 4) {
        float mx = -1e30f;
        for (int m = lane; m < NTOK; m += 32) mx = fmaxf(mx, S[n][m]);
        #pragma unroll
        for (int o = 16; o; o >>= 1) mx = fmaxf(mx, __shfl_xor_sync(0xffffffffu, mx, o));
        float sum = 0.f;
        for (int m = lane; m < NTOK; m += 32) {
            float e = __expf(S[n][m] - mx);
            S[n][m] = e;
            sum += e;
        }
        #pragma unroll
        for (int o = 16; o; o >>= 1) sum += __shfl_xor_sync(0xffffffffu, sum, o);
        float r = 1.0f / sum;
        for (int m = lane; m < NTOK; m += 32) S[n][m] *= r;
    }
    __syncthreads();

    for (int idx = tid; idx < NTOK * HD; idx += 128) {
        int n = idx >> 5, d = idx & 31;
        float o = 0.f;
        #pragma unroll
        for (int m = 0; m < NTOK; m++) o += S[n][m] * v[m][d];
        out[(size_t)(w * NTOK + n) * CH + hh * HD + d] = o;
    }
}

// ---------------- driver ----------------
extern "C" void kernel_launch(void* const* d_in, const int* in_sizes, int n_in,
                              void* d_out, int out_size) {
    const float* x      = (const float*)d_in[0];
    const float* n1g    = (const float*)d_in[1];
    const float* n1b    = (const float*)d_in[2];
    const float* qkv_w  = (const float*)d_in[3];
    const float* qkv_b  = (const float*)d_in[4];
    const float* relb   = (const float*)d_in[5];
    const float* proj_w = (const float*)d_in[6];
    const float* proj_b = (const float*)d_in[7];
    const float* n2g    = (const float*)d_in[8];
    const float* n2b    = (const float*)d_in[9];
    const float* fc1_w  = (const float*)d_in[10];
    const float* fc1_b  = (const float*)d_in[11];
    const float* fc2_w  = (const float*)d_in[12];
    const float* fc2_b  = (const float*)d_in[13];
    float* out = (float*)d_out;

    float *xw, *qkv, *y, *z, *m1;
    cudaGetSymbolAddress((void**)&xw,  g_xw);
    cudaGetSymbolAddress((void**)&qkv, g_qkv);
    cudaGetSymbolAddress((void**)&y,   g_y);
    cudaGetSymbolAddress((void**)&z,   g_z);
    cudaGetSymbolAddress((void**)&m1,  g_m1);

    const int MROWS = T_TOK / 128;  // 784

    // 1) LN1 + roll + window partition
    ln_kernel<0><<<T_TOK / 8, 256>>>(x, n1g, n1b, xw);

    // 2) qkv = xw @ qkv_w + b   (M=100352, N=768, K=256)
    sgemm<0><<<dim3(768 / 128, MROWS), 256>>>(xw, qkv_w, qkv_b, qkv, 768, 256, nullptr);

    // 3) windowed attention (writes back into xw)
    attn_kernel<<<2048 * HEADS, 128>>>(qkv, relb, xw);

    // 4) proj + window reverse + roll-back + shortcut  -> y
    sgemm<1><<<dim3(256 / 128, MROWS), 256>>>(xw, proj_w, proj_b, y, 256, 256, x);

    // 5) LN2
    ln_kernel<1><<<T_TOK / 8, 256>>>(y, n2g, n2b, z);

    // 6) fc1 + exact GELU   (N=1024, K=256)
    sgemm<2><<<dim3(1024 / 128, MROWS), 256>>>(z, fc1_w, fc1_b, m1, 1024, 256, nullptr);

    // 7) fc2 + residual -> out  (N=256, K=1024)
    sgemm<3><<<dim3(256 / 128, MROWS), 256>>>(m1, fc2_w, fc2_b, out, 256, 1024, y);
}

// round 5
// speedup vs baseline: 3.4841x; 3.4841x over previous
#include <cuda_runtime.h>
#include <math.h>
#include <stdint.h>

// ---------------- problem constants ----------------
#define BATCH   32
#define IMG_H   56
#define IMG_W   56
#define CH      256
#define WS      7
#define SHIFT_  3
#define HEADS   8
#define HD      32
#define HIDDEN  1024
#define NTOK    49
#define T_TOK   (BATCH*IMG_H*IMG_W)   // 100352 tokens

// ---------------- scratch ----------------
__device__ float g_xw [(size_t)T_TOK * CH];
__device__ float g_qkv[(size_t)T_TOK * 3 * CH];
__device__ float g_y  [(size_t)T_TOK * CH];
__device__ float g_z  [(size_t)T_TOK * CH];
__device__ float g_m1 [(size_t)T_TOK * HIDDEN];

__device__ __forceinline__ int map_token(int r) {
    int w = r / NTOK, n = r - w * NTOK;
    int b = w >> 6, widx = w & 63;
    int wh = widx >> 3, ww = widx & 7;
    int i = n / WS, j = n - i * WS;
    int h = wh * WS + i + SHIFT_;  if (h >= IMG_H) h -= IMG_H;
    int v = ww * WS + j + SHIFT_;  if (v >= IMG_W) v -= IMG_W;
    return (b * IMG_H + h) * IMG_W + v;
}

__device__ __forceinline__ uint32_t f2tf32(float f) {
    uint32_t u;
    asm("cvt.rna.tf32.f32 %0, %1;" : "=r"(u) : "f"(f));
    return u;
}

__device__ __forceinline__ void mma_tf32(float* c, const uint32_t* a, const uint32_t* b) {
    asm volatile(
        "mma.sync.aligned.m16n8k8.row.col.f32.tf32.tf32.f32 "
        "{%0,%1,%2,%3}, {%4,%5,%6,%7}, {%8,%9}, {%0,%1,%2,%3};\n"
        : "+f"(c[0]), "+f"(c[1]), "+f"(c[2]), "+f"(c[3])
        : "r"(a[0]), "r"(a[1]), "r"(a[2]), "r"(a[3]), "r"(b[0]), "r"(b[1]));
}

// ---------------- LayerNorm ----------------
template<int MODE>
__global__ void __launch_bounds__(256) ln_kernel(const float* __restrict__ in,
                                                 const float* __restrict__ gam,
                                                 const float* __restrict__ bet,
                                                 float* __restrict__ out) {
    int warp = (blockIdx.x * blockDim.x + threadIdx.x) >> 5;
    int lane = threadIdx.x & 31;
    if (warp >= T_TOK) return;
    int src = (MODE == 0) ? map_token(warp) : warp;

    const float4* row = (const float4*)(in + (size_t)src * CH);
    float4 a = row[lane];
    float4 b = row[lane + 32];

    float s = a.x + a.y + a.z + a.w + b.x + b.y + b.z + b.w;
    #pragma unroll
    for (int o = 16; o; o >>= 1) s += __shfl_xor_sync(0xffffffffu, s, o);
    float mu = s * (1.0f / CH);

    float vs = 0.f, d;
    d = a.x - mu; vs += d * d;  d = a.y - mu; vs += d * d;
    d = a.z - mu; vs += d * d;  d = a.w - mu; vs += d * d;
    d = b.x - mu; vs += d * d;  d = b.y - mu; vs += d * d;
    d = b.z - mu; vs += d * d;  d = b.w - mu; vs += d * d;
    #pragma unroll
    for (int o = 16; o; o >>= 1) vs += __shfl_xor_sync(0xffffffffu, vs, o);
    float inv = rsqrtf(vs * (1.0f / CH) + 1e-5f);

    float4 g0 = ((const float4*)gam)[lane], g1 = ((const float4*)gam)[lane + 32];
    float4 b0 = ((const float4*)bet)[lane], b1 = ((const float4*)bet)[lane + 32];
    float4 o0, o1;
    o0.x = (a.x - mu) * inv * g0.x + b0.x;  o0.y = (a.y - mu) * inv * g0.y + b0.y;
    o0.z = (a.z - mu) * inv * g0.z + b0.z;  o0.w = (a.w - mu) * inv * g0.w + b0.w;
    o1.x = (b.x - mu) * inv * g1.x + b1.x;  o1.y = (b.y - mu) * inv * g1.y + b1.y;
    o1.z = (b.z - mu) * inv * g1.z + b1.z;  o1.w = (b.w - mu) * inv * g1.w + b1.w;

    float4* orow = (float4*)(out + (size_t)warp * CH);
    orow[lane] = o0;
    orow[lane + 32] = o1;
}

// ---------------- tf32 tensor-core GEMM 128x128x16, 256 threads ----------------
// Warp tile 32x64: 2 m16 frags x 8 n8 frags. Epilogues as before:
//   EPI 0: +bias           (qkv)
//   EPI 1: scatter via map_token, +x +bias  (proj+reverse+shortcut)
//   EPI 2: gelu(+bias)     (fc1)
//   EPI 3: +extra +bias    (fc2+residual)
template<int EPI>
__global__ void __launch_bounds__(256, 2) mma_gemm(const float* __restrict__ A,
                                                   const float* __restrict__ Bw,
                                                   const float* __restrict__ bias,
                                                   float* __restrict__ Cout,
                                                   int Ndim, int Kdim,
                                                   const float* __restrict__ extra) {
    __shared__ uint32_t As[128][20];   // [m][k], pad->conflict-free frag loads
    __shared__ uint32_t Bs[16][136];   // [k][n], pad->conflict-free frag loads

    const int tid  = threadIdx.x;
    const int brow = blockIdx.y * 128;
    const int bcol = blockIdx.x * 128;
    const int warp = tid >> 5, lane = tid & 31;
    const int wm = (warp & 3) * 32, wn = (warp >> 2) * 64;
    const int lk = lane & 3, lr = lane >> 2;

    // gmem staging assignment
    const int ar = tid >> 2, ac = (tid & 3) << 2;      // A rows ar, ar+64; cols ac..ac+3
    const int bk = tid >> 4, bc = (tid & 15) << 3;     // B row bk; cols bc..bc+7
    const float* Ap = A  + (size_t)(brow + ar) * Kdim + ac;
    const float* Bp = Bw + (size_t)bk * Ndim + bcol + bc;

    float4 a0v = *(const float4*)(Ap);
    float4 a1v = *(const float4*)(Ap + (size_t)64 * Kdim);
    float4 b0v = *(const float4*)(Bp);
    float4 b1v = *(const float4*)(Bp + 4);

    float acc[2][8][4];
    #pragma unroll
    for (int i = 0; i < 2; i++)
        #pragma unroll
        for (int j = 0; j < 8; j++)
            #pragma unroll
            for (int q = 0; q < 4; q++) acc[i][j][q] = 0.f;

    const int ktiles = Kdim >> 4;
    for (int kt = 0; kt < ktiles; kt++) {
        uint4 ua0 = make_uint4(f2tf32(a0v.x), f2tf32(a0v.y), f2tf32(a0v.z), f2tf32(a0v.w));
        uint4 ua1 = make_uint4(f2tf32(a1v.x), f2tf32(a1v.y), f2tf32(a1v.z), f2tf32(a1v.w));
        uint4 ub0 = make_uint4(f2tf32(b0v.x), f2tf32(b0v.y), f2tf32(b0v.z), f2tf32(b0v.w));
        uint4 ub1 = make_uint4(f2tf32(b1v.x), f2tf32(b1v.y), f2tf32(b1v.z), f2tf32(b1v.w));
        *(uint4*)&As[ar][ac]        = ua0;
        *(uint4*)&As[ar + 64][ac]   = ua1;
        *(uint4*)&Bs[bk][bc]        = ub0;
        *(uint4*)&Bs[bk][bc + 4]    = ub1;
        __syncthreads();

        if (kt + 1 < ktiles) {
            const float* Ap2 = Ap + (kt + 1) * 16;
            const float* Bp2 = Bp + (size_t)(kt + 1) * 16 * Ndim;
            a0v = *(const float4*)(Ap2);
            a1v = *(const float4*)(Ap2 + (size_t)64 * Kdim);
            b0v = *(const float4*)(Bp2);
            b1v = *(const float4*)(Bp2 + 4);
        }

        #pragma unroll
        for (int ks = 0; ks < 2; ks++) {
            const int k0 = ks * 8;
            uint32_t af[2][4], bf[8][2];
            #pragma unroll
            for (int mi = 0; mi < 2; mi++) {
                int rb = wm + mi * 16 + lr;
                af[mi][0] = As[rb][k0 + lk];
                af[mi][1] = As[rb + 8][k0 + lk];
                af[mi][2] = As[rb][k0 + lk + 4];
                af[mi][3] = As[rb + 8][k0 + lk + 4];
            }
            #pragma unroll
            for (int ni = 0; ni < 8; ni++) {
                int cb = wn + ni * 8 + lr;
                bf[ni][0] = Bs[k0 + lk][cb];
                bf[ni][1] = Bs[k0 + lk + 4][cb];
            }
            #pragma unroll
            for (int mi = 0; mi < 2; mi++)
                #pragma unroll
                for (int ni = 0; ni < 8; ni++)
                    mma_tf32(acc[mi][ni], af[mi], bf[ni]);
        }
        __syncthreads();
    }

    // epilogue: per (mi,ni): rows r0,r0+8, cols col,col+1
    #pragma unroll
    for (int mi = 0; mi < 2; mi++) {
        int r0 = brow + wm + mi * 16 + lr;
        int r1 = r0 + 8;
        int t0 = (EPI == 1) ? map_token(r0) : r0;
        int t1 = (EPI == 1) ? map_token(r1) : r1;
        #pragma unroll
        for (int ni = 0; ni < 8; ni++) {
            int col = bcol + wn + ni * 8 + 2 * lk;
            float2 bs = *(const float2*)(bias + col);
            float v0 = acc[mi][ni][0] + bs.x, v1 = acc[mi][ni][1] + bs.y;
            float v2 = acc[mi][ni][2] + bs.x, v3 = acc[mi][ni][3] + bs.y;
            if (EPI == 0) {
                *(float2*)(Cout + (size_t)r0 * Ndim + col) = make_float2(v0, v1);
                *(float2*)(Cout + (size_t)r1 * Ndim + col) = make_float2(v2, v3);
            } else if (EPI == 1) {
                float2 e0 = *(const float2*)(extra + (size_t)t0 * CH + col);
                float2 e1 = *(const float2*)(extra + (size_t)t1 * CH + col);
                *(float2*)(Cout + (size_t)t0 * CH + col) = make_float2(e0.x + v0, e0.y + v1);
                *(float2*)(Cout + (size_t)t1 * CH + col) = make_float2(e1.x + v2, e1.y + v3);
            } else if (EPI == 2) {
                const float r2i = 0.70710678118654752f;
                v0 = 0.5f * v0 * (1.0f + erff(v0 * r2i));
                v1 = 0.5f * v1 * (1.0f + erff(v1 * r2i));
                v2 = 0.5f * v2 * (1.0f + erff(v2 * r2i));
                v3 = 0.5f * v3 * (1.0f + erff(v3 * r2i));
                *(float2*)(Cout + (size_t)r0 * Ndim + col) = make_float2(v0, v1);
                *(float2*)(Cout + (size_t)r1 * Ndim + col) = make_float2(v2, v3);
            } else {
                float2 e0 = *(const float2*)(extra + (size_t)r0 * CH + col);
                float2 e1 = *(const float2*)(extra + (size_t)r1 * CH + col);
                *(float2*)(Cout + (size_t)r0 * CH + col) = make_float2(e0.x + v0, e0.y + v1);
                *(float2*)(Cout + (size_t)r1 * CH + col) = make_float2(e1.x + v2, e1.y + v3);
            }
        }
    }
}

// ---------------- attention: one block per (window, head) ----------------
__global__ void __launch_bounds__(128) attn_kernel(const float* __restrict__ qkv,
                                                   const float* __restrict__ rel_bias,
                                                   float* __restrict__ out) {
    const int blk = blockIdx.x;
    const int w   = blk >> 3;
    const int hh  = blk & 7;
    const int tid = threadIdx.x;

    __shared__ float q[NTOK][HD + 1];
    __shared__ float k[NTOK][HD + 1];
    __shared__ float v[NTOK][HD + 1];
    __shared__ float S[NTOK][NTOK + 3];

    const float scale = 0.17677669529663687f;

    for (int idx = tid; idx < NTOK * 8; idx += 128) {
        int n = idx >> 3, c4 = (idx & 7) << 2;
        size_t base = (size_t)(w * NTOK + n) * (3 * CH) + hh * HD + c4;
        float4 qv = *(const float4*)(qkv + base);
        float4 kv = *(const float4*)(qkv + base + CH);
        float4 vv = *(const float4*)(qkv + base + 2 * CH);
        q[n][c4 + 0] = qv.x * scale; q[n][c4 + 1] = qv.y * scale;
        q[n][c4 + 2] = qv.z * scale; q[n][c4 + 3] = qv.w * scale;
        k[n][c4 + 0] = kv.x; k[n][c4 + 1] = kv.y; k[n][c4 + 2] = kv.z; k[n][c4 + 3] = kv.w;
        v[n][c4 + 0] = vv.x; v[n][c4 + 1] = vv.y; v[n][c4 + 2] = vv.z; v[n][c4 + 3] = vv.w;
    }
    __syncthreads();

    const int widx = w & 63;
    const int wh = widx >> 3, ww = widx & 7;

    for (int idx = tid; idx < NTOK * NTOK; idx += 128) {
        int n = idx / NTOK, m = idx - n * NTOK;
        float s = 0.f;
        #pragma unroll
        for (int d = 0; d < HD; d++) s += q[n][d] * k[m][d];
        int in_ = n / WS, jn = n - in_ * WS;
        int im  = m / WS, jm = m - im * WS;
        s += rel_bias[((im - in_ + 6) * 13 + (jm - jn + 6)) * HEADS + hh];
        int hn = wh * WS + in_, wn = ww * WS + jn;
        int hm = wh * WS + im,  wm = ww * WS + jm;
        int tn = (hn < 49 ? 0 : (hn < 53 ? 1 : 2)) * 3 + (wn < 49 ? 0 : (wn < 53 ? 1 : 2));
        int tm = (hm < 49 ? 0 : (hm < 53 ? 1 : 2)) * 3 + (wm < 49 ? 0 : (wm < 53 ? 1 : 2));
        if (tn != tm) s -= 100.0f;
        S[n][m] = s;
    }
    __syncthreads();

    const int warp = tid >> 5, lane = tid & 31;
    for (int n = warp; n < NTOK; n += 4) {
        float mx = -1e30f;
        for (int m = lane; m < NTOK; m += 32) mx = fmaxf(mx, S[n][m]);
        #pragma unroll
        for (int o = 16; o; o >>= 1) mx = fmaxf(mx, __shfl_xor_sync(0xffffffffu, mx, o));
        float sum = 0.f;
        for (int m = lane; m < NTOK; m += 32) {
            float e = __expf(S[n][m] - mx);
            S[n][m] = e;
            sum += e;
        }
        #pragma unroll
        for (int o = 16; o; o >>= 1) sum += __shfl_xor_sync(0xffffffffu, sum, o);
        float r = 1.0f / sum;
        for (int m = lane; m < NTOK; m += 32) S[n][m] *= r;
    }
    __syncthreads();

    for (int idx = tid; idx < NTOK * HD; idx += 128) {
        int n = idx >> 5, d = idx & 31;
        float o = 0.f;
        #pragma unroll
        for (int m = 0; m < NTOK; m++) o += S[n][m] * v[m][d];
        out[(size_t)(w * NTOK + n) * CH + hh * HD + d] = o;
    }
}

// ---------------- driver ----------------
extern "C" void kernel_launch(void* const* d_in, const int* in_sizes, int n_in,
                              void* d_out, int out_size) {
    const float* x      = (const float*)d_in[0];
    const float* n1g    = (const float*)d_in[1];
    const float* n1b    = (const float*)d_in[2];
    const float* qkv_w  = (const float*)d_in[3];
    const float* qkv_b  = (const float*)d_in[4];
    const float* relb   = (const float*)d_in[5];
    const float* proj_w = (const float*)d_in[6];
    const float* proj_b = (const float*)d_in[7];
    const float* n2g    = (const float*)d_in[8];
    const float* n2b    = (const float*)d_in[9];
    const float* fc1_w  = (const float*)d_in[10];
    const float* fc1_b  = (const float*)d_in[11];
    const float* fc2_w  = (const float*)d_in[12];
    const float* fc2_b  = (const float*)d_in[13];
    float* out = (float*)d_out;

    float *xw, *qkv, *y, *z, *m1;
    cudaGetSymbolAddress((void**)&xw,  g_xw);
    cudaGetSymbolAddress((void**)&qkv, g_qkv);
    cudaGetSymbolAddress((void**)&y,   g_y);
    cudaGetSymbolAddress((void**)&z,   g_z);
    cudaGetSymbolAddress((void**)&m1,  g_m1);

    const int MROWS = T_TOK / 128;  // 784

    ln_kernel<0><<<T_TOK / 8, 256>>>(x, n1g, n1b, xw);
    mma_gemm<0><<<dim3(768 / 128, MROWS), 256>>>(xw, qkv_w, qkv_b, qkv, 768, 256, nullptr);
    attn_kernel<<<2048 * HEADS, 128>>>(qkv, relb, xw);
    mma_gemm<1><<<dim3(256 / 128, MROWS), 256>>>(xw, proj_w, proj_b, y, 256, 256, x);
    ln_kernel<1><<<T_TOK / 8, 256>>>(y, n2g, n2b, z);
    mma_gemm<2><<<dim3(1024 / 128, MROWS), 256>>>(z, fc1_w, fc1_b, m1, 1024, 256, nullptr);
    mma_gemm<3><<<dim3(256 / 128, MROWS), 256>>>(m1, fc2_w, fc2_b, out, 256, 1024, y);
}

// round 7
// speedup vs baseline: 3.6792x; 1.0560x over previous
#include <cuda_runtime.h>
#include <math.h>
#include <stdint.h>

// ---------------- problem constants ----------------
#define BATCH   32
#define IMG_H   56
#define IMG_W   56
#define CH      256
#define WS      7
#define SHIFT_  3
#define HEADS   8
#define HD      32
#define HIDDEN  1024
#define NTOK    49
#define T_TOK   (BATCH*IMG_H*IMG_W)   // 100352 tokens

// ---------------- scratch ----------------
__device__ uint32_t g_xw [(size_t)T_TOK * CH];        // tf32 bits (GEMM A inputs)
__device__ float    g_qkv[(size_t)T_TOK * 3 * CH];
__device__ float    g_y  [(size_t)T_TOK * CH];
__device__ uint32_t g_z  [(size_t)T_TOK * CH];        // tf32 bits
__device__ uint32_t g_m1 [(size_t)T_TOK * HIDDEN];    // tf32 bits
// tf32-converted weights
__device__ uint32_t g_wq [256 * 768];
__device__ uint32_t g_wp [256 * 256];
__device__ uint32_t g_w1 [256 * 1024];
__device__ uint32_t g_w2 [1024 * 256];

__device__ __forceinline__ int map_token(int r) {
    int w = r / NTOK, n = r - w * NTOK;
    int b = w >> 6, widx = w & 63;
    int wh = widx >> 3, ww = widx & 7;
    int i = n / WS, j = n - i * WS;
    int h = wh * WS + i + SHIFT_;  if (h >= IMG_H) h -= IMG_H;
    int v = ww * WS + j + SHIFT_;  if (v >= IMG_W) v -= IMG_W;
    return (b * IMG_H + h) * IMG_W + v;
}

__device__ __forceinline__ uint32_t f2tf32(float f) {
    uint32_t u;
    asm("cvt.rna.tf32.f32 %0, %1;" : "=r"(u) : "f"(f));
    return u;
}

__device__ __forceinline__ void mma_tf32(float* c, const uint32_t* a, const uint32_t* b) {
    asm volatile(
        "mma.sync.aligned.m16n8k8.row.col.f32.tf32.tf32.f32 "
        "{%0,%1,%2,%3}, {%4,%5,%6,%7}, {%8,%9}, {%0,%1,%2,%3};\n"
        : "+f"(c[0]), "+f"(c[1]), "+f"(c[2]), "+f"(c[3])
        : "r"(a[0]), "r"(a[1]), "r"(a[2]), "r"(a[3]), "r"(b[0]), "r"(b[1]));
}

__device__ __forceinline__ void cp16(uint32_t smem_addr, const void* gptr) {
    asm volatile("cp.async.cg.shared.global [%0], [%1], 16;\n" :: "r"(smem_addr), "l"(gptr));
}
__device__ __forceinline__ void cp_commit() { asm volatile("cp.async.commit_group;\n"); }
__device__ __forceinline__ void cp_wait0()  { asm volatile("cp.async.wait_group 0;\n"); }

// ---------------- weight conversion ----------------
__global__ void __launch_bounds__(256) conv_tf32(const float* __restrict__ in,
                                                 uint32_t* __restrict__ out, int n) {
    for (int i = blockIdx.x * blockDim.x + threadIdx.x; i < n; i += gridDim.x * blockDim.x)
        out[i] = f2tf32(in[i]);
}

// ---------------- LayerNorm (writes tf32 bit-patterns) ----------------
template<int MODE>
__global__ void __launch_bounds__(256) ln_kernel(const float* __restrict__ in,
                                                 const float* __restrict__ gam,
                                                 const float* __restrict__ bet,
                                                 uint32_t* __restrict__ out) {
    int warp = (blockIdx.x * blockDim.x + threadIdx.x) >> 5;
    int lane = threadIdx.x & 31;
    if (warp >= T_TOK) return;
    int src = (MODE == 0) ? map_token(warp) : warp;

    const float4* row = (const float4*)(in + (size_t)src * CH);
    float4 a = row[lane];
    float4 b = row[lane + 32];

    float s = a.x + a.y + a.z + a.w + b.x + b.y + b.z + b.w;
    #pragma unroll
    for (int o = 16; o; o >>= 1) s += __shfl_xor_sync(0xffffffffu, s, o);
    float mu = s * (1.0f / CH);

    float vs = 0.f, d;
    d = a.x - mu; vs += d * d;  d = a.y - mu; vs += d * d;
    d = a.z - mu; vs += d * d;  d = a.w - mu; vs += d * d;
    d = b.x - mu; vs += d * d;  d = b.y - mu; vs += d * d;
    d = b.z - mu; vs += d * d;  d = b.w - mu; vs += d * d;
    #pragma unroll
    for (int o = 16; o; o >>= 1) vs += __shfl_xor_sync(0xffffffffu, vs, o);
    float inv = rsqrtf(vs * (1.0f / CH) + 1e-5f);

    float4 g0 = ((const float4*)gam)[lane], g1 = ((const float4*)gam)[lane + 32];
    float4 b0 = ((const float4*)bet)[lane], b1 = ((const float4*)bet)[lane + 32];
    uint4 o0, o1;
    o0.x = f2tf32((a.x - mu) * inv * g0.x + b0.x);  o0.y = f2tf32((a.y - mu) * inv * g0.y + b0.y);
    o0.z = f2tf32((a.z - mu) * inv * g0.z + b0.z);  o0.w = f2tf32((a.w - mu) * inv * g0.w + b0.w);
    o1.x = f2tf32((b.x - mu) * inv * g1.x + b1.x);  o1.y = f2tf32((b.y - mu) * inv * g1.y + b1.y);
    o1.z = f2tf32((b.z - mu) * inv * g1.z + b1.z);  o1.w = f2tf32((b.w - mu) * inv * g1.w + b1.w);

    uint4* orow = (uint4*)(out + (size_t)warp * CH);
    orow[lane] = o0;
    orow[lane + 32] = o1;
}

// ---------------- tf32 GEMM 128x128x16, cp.async double-buffered ----------------
// A, Bw are pre-converted tf32 bit patterns. Epilogues:
//   EPI 0: +bias -> fp32                       (qkv)
//   EPI 1: scatter map_token, +x +bias -> fp32 (proj+reverse+shortcut)
//   EPI 2: gelu(+bias) -> tf32 bits            (fc1)
//   EPI 3: +extra +bias -> fp32                (fc2+residual)
template<int EPI>
__global__ void __launch_bounds__(256, 2) mma_gemm(const uint32_t* __restrict__ A,
                                                   const uint32_t* __restrict__ Bw,
                                                   const float* __restrict__ bias,
                                                   float* __restrict__ Cout,
                                                   int Ndim, int Kdim,
                                                   const float* __restrict__ extra) {
    __shared__ uint32_t As[2][128][20];
    __shared__ uint32_t Bs[2][16][136];

    const int tid  = threadIdx.x;
    const int brow = blockIdx.y * 128;
    const int bcol = blockIdx.x * 128;
    const int warp = tid >> 5, lane = tid & 31;
    const int wm = (warp & 3) * 32, wn = (warp >> 2) * 64;
    const int lk = lane & 3, lr = lane >> 2;

    const int ar = tid >> 2, ac = (tid & 3) << 2;
    const int bk = tid >> 4, bc = (tid & 15) << 3;
    const uint32_t* Ap = A  + (size_t)(brow + ar) * Kdim + ac;
    const uint32_t* Bp = Bw + (size_t)bk * Ndim + bcol + bc;

    uint32_t sA0[2], sA1[2], sB0[2], sB1[2];
    #pragma unroll
    for (int b = 0; b < 2; b++) {
        sA0[b] = (uint32_t)__cvta_generic_to_shared(&As[b][ar][ac]);
        sA1[b] = (uint32_t)__cvta_generic_to_shared(&As[b][ar + 64][ac]);
        sB0[b] = (uint32_t)__cvta_generic_to_shared(&Bs[b][bk][bc]);
        sB1[b] = (uint32_t)__cvta_generic_to_shared(&Bs[b][bk][bc + 4]);
    }

    float acc[2][8][4];
    #pragma unroll
    for (int i = 0; i < 2; i++)
        #pragma unroll
        for (int j = 0; j < 8; j++)
            #pragma unroll
            for (int q = 0; q < 4; q++) acc[i][j][q] = 0.f;

    const int ktiles = Kdim >> 4;
    // prologue: tile 0 -> buf 0
    cp16(sA0[0], Ap);
    cp16(sA1[0], Ap + (size_t)64 * Kdim);
    cp16(sB0[0], Bp);
    cp16(sB1[0], Bp + 4);
    cp_commit();

    for (int kt = 0; kt < ktiles; kt++) {
        cp_wait0();
        __syncthreads();

        if (kt + 1 < ktiles) {
            const int nb = (kt + 1) & 1;
            const uint32_t* Ap2 = Ap + (kt + 1) * 16;
            const uint32_t* Bp2 = Bp + (size_t)(kt + 1) * 16 * Ndim;
            cp16(sA0[nb], Ap2);
            cp16(sA1[nb], Ap2 + (size_t)64 * Kdim);
            cp16(sB0[nb], Bp2);
            cp16(sB1[nb], Bp2 + 4);
            cp_commit();
        }

        const int cb_ = kt & 1;
        #pragma unroll
        for (int ks = 0; ks < 2; ks++) {
            const int k0 = ks * 8;
            uint32_t af[2][4], bf[8][2];
            #pragma unroll
            for (int mi = 0; mi < 2; mi++) {
                int rb = wm + mi * 16 + lr;
                af[mi][0] = As[cb_][rb][k0 + lk];
                af[mi][1] = As[cb_][rb + 8][k0 + lk];
                af[mi][2] = As[cb_][rb][k0 + lk + 4];
                af[mi][3] = As[cb_][rb + 8][k0 + lk + 4];
            }
            #pragma unroll
            for (int ni = 0; ni < 8; ni++) {
                int cbn = wn + ni * 8 + lr;
                bf[ni][0] = Bs[cb_][k0 + lk][cbn];
                bf[ni][1] = Bs[cb_][k0 + lk + 4][cbn];
            }
            #pragma unroll
            for (int mi = 0; mi < 2; mi++)
                #pragma unroll
                for (int ni = 0; ni < 8; ni++)
                    mma_tf32(acc[mi][ni], af[mi], bf[ni]);
        }
        __syncthreads();
    }

    #pragma unroll
    for (int mi = 0; mi < 2; mi++) {
        int r0 = brow + wm + mi * 16 + lr;
        int r1 = r0 + 8;
        int t0 = (EPI == 1) ? map_token(r0) : r0;
        int t1 = (EPI == 1) ? map_token(r1) : r1;
        #pragma unroll
        for (int ni = 0; ni < 8; ni++) {
            int col = bcol + wn + ni * 8 + 2 * lk;
            float2 bs = *(const float2*)(bias + col);
            float v0 = acc[mi][ni][0] + bs.x, v1 = acc[mi][ni][1] + bs.y;
            float v2 = acc[mi][ni][2] + bs.x, v3 = acc[mi][ni][3] + bs.y;
            if (EPI == 0) {
                *(float2*)(Cout + (size_t)r0 * Ndim + col) = make_float2(v0, v1);
                *(float2*)(Cout + (size_t)r1 * Ndim + col) = make_float2(v2, v3);
            } else if (EPI == 1) {
                float2 e0 = *(const float2*)(extra + (size_t)t0 * CH + col);
                float2 e1 = *(const float2*)(extra + (size_t)t1 * CH + col);
                *(float2*)(Cout + (size_t)t0 * CH + col) = make_float2(e0.x + v0, e0.y + v1);
                *(float2*)(Cout + (size_t)t1 * CH + col) = make_float2(e1.x + v2, e1.y + v3);
            } else if (EPI == 2) {
                const float r2i = 0.70710678118654752f;
                v0 = 0.5f * v0 * (1.0f + erff(v0 * r2i));
                v1 = 0.5f * v1 * (1.0f + erff(v1 * r2i));
                v2 = 0.5f * v2 * (1.0f + erff(v2 * r2i));
                v3 = 0.5f * v3 * (1.0f + erff(v3 * r2i));
                uint32_t* Co = (uint32_t*)Cout;
                Co[(size_t)r0 * Ndim + col]     = f2tf32(v0);
                Co[(size_t)r0 * Ndim + col + 1] = f2tf32(v1);
                Co[(size_t)r1 * Ndim + col]     = f2tf32(v2);
                Co[(size_t)r1 * Ndim + col + 1] = f2tf32(v3);
            } else {
                float2 e0 = *(const float2*)(extra + (size_t)r0 * CH + col);
                float2 e1 = *(const float2*)(extra + (size_t)r1 * CH + col);
                *(float2*)(Cout + (size_t)r0 * CH + col) = make_float2(e0.x + v0, e0.y + v1);
                *(float2*)(Cout + (size_t)r1 * CH + col) = make_float2(e1.x + v2, e1.y + v3);
            }
        }
    }
}

// ---------------- attention (fp32 in, tf32-bit out) ----------------
__global__ void __launch_bounds__(128) attn_kernel(const float* __restrict__ qkv,
                                                   const float* __restrict__ rel_bias,
                                                   uint32_t* __restrict__ out) {
    const int blk = blockIdx.x;
    const int w   = blk >> 3;
    const int hh  = blk & 7;
    const int tid = threadIdx.x;

    __shared__ float q[NTOK][HD + 1];
    __shared__ float k[NTOK][HD + 1];
    __shared__ float v[NTOK][HD + 1];
    __shared__ float S[NTOK][NTOK + 3];

    const float scale = 0.17677669529663687f;

    for (int idx = tid; idx < NTOK * 8; idx += 128) {
        int n = idx >> 3, c4 = (idx & 7) << 2;
        size_t base = (size_t)(w * NTOK + n) * (3 * CH) + hh * HD + c4;
        float4 qv = *(const float4*)(qkv + base);
        float4 kv = *(const float4*)(qkv + base + CH);
        float4 vv = *(const float4*)(qkv + base + 2 * CH);
        q[n][c4 + 0] = qv.x * scale; q[n][c4 + 1] = qv.y * scale;
        q[n][c4 + 2] = qv.z * scale; q[n][c4 + 3] = qv.w * scale;
        k[n][c4 + 0] = kv.x; k[n][c4 + 1] = kv.y; k[n][c4 + 2] = kv.z; k[n][c4 + 3] = kv.w;
        v[n][c4 + 0] = vv.x; v[n][c4 + 1] = vv.y; v[n][c4 + 2] = vv.z; v[n][c4 + 3] = vv.w;
    }
    __syncthreads();

    const int widx = w & 63;
    const int wh = widx >> 3, ww = widx & 7;

    for (int idx = tid; idx < NTOK * NTOK; idx += 128) {
        int n = idx / NTOK, m = idx - n * NTOK;
        float s = 0.f;
        #pragma unroll
        for (int d = 0; d < HD; d++) s += q[n][d] * k[m][d];
        int in_ = n / WS, jn = n - in_ * WS;
        int im  = m / WS, jm = m - im * WS;
        s += rel_bias[((im - in_ + 6) * 13 + (jm - jn + 6)) * HEADS + hh];
        int hn = wh * WS + in_, wn = ww * WS + jn;
        int hm = wh * WS + im,  wm = ww * WS + jm;
        int tn = (hn < 49 ? 0 : (hn < 53 ? 1 : 2)) * 3 + (wn < 49 ? 0 : (wn < 53 ? 1 : 2));
        int tm = (hm < 49 ? 0 : (hm < 53 ? 1 : 2)) * 3 + (wm < 49 ? 0 : (wm < 53 ? 1 : 2));
        if (tn != tm) s -= 100.0f;
        S[n][m] = s;
    }
    __syncthreads();

    const int warp = tid >> 5, lane = tid & 31;
    for (int n = warp; n < NTOK; n += 4) {
        float mx = -1e30f;
        for (int m = lane; m < NTOK; m += 32) mx = fmaxf(mx, S[n][m]);
        #pragma unroll
        for (int o = 16; o; o >>= 1) mx = fmaxf(mx, __shfl_xor_sync(0xffffffffu, mx, o));
        float sum = 0.f;
        for (int m = lane; m < NTOK; m += 32) {
            float e = __expf(S[n][m] - mx);
            S[n][m] = e;
            sum += e;
        }
        #pragma unroll
        for (int o = 16; o; o >>= 1) sum += __shfl_xor_sync(0xffffffffu, sum, o);
        float r = 1.0f / sum;
        for (int m = lane; m < NTOK; m += 32) S[n][m] *= r;
    }
    __syncthreads();

    for (int idx = tid; idx < NTOK * HD; idx += 128) {
        int n = idx >> 5, d = idx & 31;
        float o = 0.f;
        #pragma unroll
        for (int m = 0; m < NTOK; m++) o += S[n][m] * v[m][d];
        out[(size_t)(w * NTOK + n) * CH + hh * HD + d] = f2tf32(o);
    }
}

// ---------------- driver ----------------
extern "C" void kernel_launch(void* const* d_in, const int* in_sizes, int n_in,
                              void* d_out, int out_size) {
    const float* x      = (const float*)d_in[0];
    const float* n1g    = (const float*)d_in[1];
    const float* n1b    = (const float*)d_in[2];
    const float* qkv_w  = (const float*)d_in[3];
    const float* qkv_b  = (const float*)d_in[4];
    const float* relb   = (const float*)d_in[5];
    const float* proj_w = (const float*)d_in[6];
    const float* proj_b = (const float*)d_in[7];
    const float* n2g    = (const float*)d_in[8];
    const float* n2b    = (const float*)d_in[9];
    const float* fc1_w  = (const float*)d_in[10];
    const float* fc1_b  = (const float*)d_in[11];
    const float* fc2_w  = (const float*)d_in[12];
    const float* fc2_b  = (const float*)d_in[13];
    float* out = (float*)d_out;

    uint32_t *xw, *z, *m1, *wq, *wp, *w1, *w2;
    float *qkv, *y;
    cudaGetSymbolAddress((void**)&xw,  g_xw);
    cudaGetSymbolAddress((void**)&qkv, g_qkv);
    cudaGetSymbolAddress((void**)&y,   g_y);
    cudaGetSymbolAddress((void**)&z,   g_z);
    cudaGetSymbolAddress((void**)&m1,  g_m1);
    cudaGetSymbolAddress((void**)&wq,  g_wq);
    cudaGetSymbolAddress((void**)&wp,  g_wp);
    cudaGetSymbolAddress((void**)&w1,  g_w1);
    cudaGetSymbolAddress((void**)&w2,  g_w2);

    const int MROWS = T_TOK / 128;  // 784

    // weight conversion (cheap, overlappable)
    conv_tf32<<<192, 256>>>(qkv_w,  wq, 256 * 768);
    conv_tf32<<<64,  256>>>(proj_w, wp, 256 * 256);
    conv_tf32<<<256, 256>>>(fc1_w,  w1, 256 * 1024);
    conv_tf32<<<256, 256>>>(fc2_w,  w2, 1024 * 256);

    ln_kernel<0><<<T_TOK / 8, 256>>>(x, n1g, n1b, xw);
    mma_gemm<0><<<dim3(768 / 128, MROWS), 256>>>(xw, wq, qkv_b, qkv, 768, 256, nullptr);
    attn_kernel<<<2048 * HEADS, 128>>>(qkv, relb, xw);
    mma_gemm<1><<<dim3(256 / 128, MROWS), 256>>>(xw, wp, proj_b, y, 256, 256, x);
    ln_kernel<1><<<T_TOK / 8, 256>>>(y, n2g, n2b, z);
    mma_gemm<2><<<dim3(1024 / 128, MROWS), 256>>>(z, w1, fc1_b, (float*)m1, 1024, 256, nullptr);
    mma_gemm<3><<<dim3(256 / 128, MROWS), 256>>>(m1, w2, fc2_b, out, 256, 1024, y);
}

// round 10
// speedup vs baseline: 5.3925x; 1.4657x over previous
#include <cuda_runtime.h>
#include <cuda_bf16.h>
#include <math.h>
#include <stdint.h>

// ---------------- problem constants ----------------
#define BATCH   32
#define IMG_H   56
#define IMG_W   56
#define CH      256
#define WS      7
#define SHIFT_  3
#define HEADS   8
#define HD      32
#define HIDDEN  1024
#define NTOK    49
#define T_TOK   (BATCH*IMG_H*IMG_W)   // 100352

typedef __nv_bfloat16 bf16;
typedef __nv_bfloat162 bf162;

// ---------------- scratch ----------------
__device__ bf16  g_xw [(size_t)T_TOK * CH];        // bf16: LN1 out, then attn out
__device__ float g_qkv[(size_t)T_TOK * 3 * CH];
__device__ float g_y  [(size_t)T_TOK * CH];
__device__ bf16  g_z  [(size_t)T_TOK * CH];        // bf16 LN2 out
__device__ bf16  g_m1 [(size_t)T_TOK * HIDDEN];    // bf16 gelu out
__device__ bf16  g_wq [256 * 768];
__device__ bf16  g_wp [256 * 256];
__device__ bf16  g_w1 [256 * 1024];
__device__ bf16  g_w2 [1024 * 256];

__device__ __forceinline__ int map_token(int r) {
    int w = r / NTOK, n = r - w * NTOK;
    int b = w >> 6, widx = w & 63;
    int wh = widx >> 3, ww = widx & 7;
    int i = n / WS, j = n - i * WS;
    int h = wh * WS + i + SHIFT_;  if (h >= IMG_H) h -= IMG_H;
    int v = ww * WS + j + SHIFT_;  if (v >= IMG_W) v -= IMG_W;
    return (b * IMG_H + h) * IMG_W + v;
}

__device__ __forceinline__ void mma_bf16(float* c, const uint32_t* a, const uint32_t* b) {
    asm volatile(
        "mma.sync.aligned.m16n8k16.row.col.f32.bf16.bf16.f32 "
        "{%0,%1,%2,%3}, {%4,%5,%6,%7}, {%8,%9}, {%0,%1,%2,%3};\n"
        : "+f"(c[0]), "+f"(c[1]), "+f"(c[2]), "+f"(c[3])
        : "r"(a[0]), "r"(a[1]), "r"(a[2]), "r"(a[3]), "r"(b[0]), "r"(b[1]));
}
__device__ __forceinline__ void ldm_x4(uint32_t& r0, uint32_t& r1, uint32_t& r2, uint32_t& r3, uint32_t a) {
    asm volatile("ldmatrix.sync.aligned.m8n8.x4.shared.b16 {%0,%1,%2,%3}, [%4];"
                 : "=r"(r0), "=r"(r1), "=r"(r2), "=r"(r3) : "r"(a));
}
__device__ __forceinline__ void ldm_x4t(uint32_t& r0, uint32_t& r1, uint32_t& r2, uint32_t& r3, uint32_t a) {
    asm volatile("ldmatrix.sync.aligned.m8n8.x4.trans.shared.b16 {%0,%1,%2,%3}, [%4];"
                 : "=r"(r0), "=r"(r1), "=r"(r2), "=r"(r3) : "r"(a));
}
__device__ __forceinline__ void cp16(uint32_t smem_addr, const void* gptr) {
    asm volatile("cp.async.cg.shared.global [%0], [%1], 16;\n" :: "r"(smem_addr), "l"(gptr));
}
__device__ __forceinline__ void cp_commit() { asm volatile("cp.async.commit_group;\n"); }
__device__ __forceinline__ void cp_wait0()  { asm volatile("cp.async.wait_group 0;\n"); }

// ---------------- weight conversion fp32 -> bf16 ----------------
__global__ void __launch_bounds__(256) conv_bf16(const float* __restrict__ in,
                                                 bf16* __restrict__ out, int n) {
    int i = (blockIdx.x * blockDim.x + threadIdx.x) * 2;
    for (; i < n; i += gridDim.x * blockDim.x * 2) {
        float2 f = *(const float2*)(in + i);
        *(bf162*)(out + i) = __floats2bfloat162_rn(f.x, f.y);
    }
}

// ---------------- LayerNorm -> bf16 ----------------
template<int MODE>
__global__ void __launch_bounds__(256) ln_kernel(const float* __restrict__ in,
                                                 const float* __restrict__ gam,
                                                 const float* __restrict__ bet,
                                                 bf16* __restrict__ out) {
    int warp = (blockIdx.x * blockDim.x + threadIdx.x) >> 5;
    int lane = threadIdx.x & 31;
    if (warp >= T_TOK) return;
    int src = (MODE == 0) ? map_token(warp) : warp;

    const float4* row = (const float4*)(in + (size_t)src * CH);
    float4 a = row[lane];
    float4 b = row[lane + 32];

    float s = a.x + a.y + a.z + a.w + b.x + b.y + b.z + b.w;
    #pragma unroll
    for (int o = 16; o; o >>= 1) s += __shfl_xor_sync(0xffffffffu, s, o);
    float mu = s * (1.0f / CH);

    float vs = 0.f, d;
    d = a.x - mu; vs += d * d;  d = a.y - mu; vs += d * d;
    d = a.z - mu; vs += d * d;  d = a.w - mu; vs += d * d;
    d = b.x - mu; vs += d * d;  d = b.y - mu; vs += d * d;
    d = b.z - mu; vs += d * d;  d = b.w - mu; vs += d * d;
    #pragma unroll
    for (int o = 16; o; o >>= 1) vs += __shfl_xor_sync(0xffffffffu, vs, o);
    float inv = rsqrtf(vs * (1.0f / CH) + 1e-5f);

    float4 g0 = ((const float4*)gam)[lane], g1 = ((const float4*)gam)[lane + 32];
    float4 b0 = ((const float4*)bet)[lane], b1 = ((const float4*)bet)[lane + 32];

    bf162* orow = (bf162*)(out + (size_t)warp * CH);
    orow[2 * lane]          = __floats2bfloat162_rn((a.x - mu) * inv * g0.x + b0.x, (a.y - mu) * inv * g0.y + b0.y);
    orow[2 * lane + 1]      = __floats2bfloat162_rn((a.z - mu) * inv * g0.z + b0.z, (a.w - mu) * inv * g0.w + b0.w);
    orow[64 + 2 * lane]     = __floats2bfloat162_rn((b.x - mu) * inv * g1.x + b1.x, (b.y - mu) * inv * g1.y + b1.y);
    orow[64 + 2 * lane + 1] = __floats2bfloat162_rn((b.z - mu) * inv * g1.z + b1.z, (b.w - mu) * inv * g1.w + b1.w);
}

// ---------------- bf16 GEMM 128x128x32, ldmatrix + single-sync 2-stage ----------------
//   EPI 0: +bias -> fp32                       (qkv)
//   EPI 1: scatter map_token, +x +bias -> fp32 (proj+reverse+shortcut)
//   EPI 2: gelu(+bias) -> bf16                 (fc1)
//   EPI 3: +extra +bias -> fp32                (fc2+residual)
#define ASTRIDE 40
#define BSTRIDE 136
#define A_STAGE (128 * ASTRIDE * 2)   // bytes
#define B_STAGE (32 * BSTRIDE * 2)

template<int EPI>
__global__ void __launch_bounds__(256, 2) mma_gemm(const bf16* __restrict__ A,
                                                   const bf16* __restrict__ Bw,
                                                   const float* __restrict__ bias,
                                                   float* __restrict__ Cout,
                                                   int Ndim, int Kdim,
                                                   const float* __restrict__ extra) {
    __shared__ bf16 As[2][128][ASTRIDE];
    __shared__ bf16 Bs[2][32][BSTRIDE];

    const int tid  = threadIdx.x;
    const int brow = blockIdx.y * 128;
    const int bcol = blockIdx.x * 128;
    const int warp = tid >> 5, lane = tid & 31;
    const int wm = (warp & 3) * 32, wn = (warp >> 2) * 64;
    const int lk = lane & 3, lr = lane >> 2;

    // cp.async staging: A rows ar, cols ac..ac+15 ; B row bk, cols bc..bc+15
    const int ar = tid >> 1, ac = (tid & 1) * 16;
    const int bk = tid >> 3, bc = (tid & 7) * 16;
    const bf16* Ap = A  + (size_t)(brow + ar) * Kdim + ac;
    const bf16* Bp = Bw + (size_t)bk * Ndim + bcol + bc;

    uint32_t sA[2], sB[2];
    #pragma unroll
    for (int s = 0; s < 2; s++) {
        sA[s] = (uint32_t)__cvta_generic_to_shared(&As[s][ar][ac]);
        sB[s] = (uint32_t)__cvta_generic_to_shared(&Bs[s][bk][bc]);
    }

    // ldmatrix base addresses (stage 0, k-step 0)
    const int lrow = lane & 15, lsel = lane >> 4;
    uint32_t laA0 = (uint32_t)__cvta_generic_to_shared(&As[0][wm + lrow][lsel * 8]);
    uint32_t laA1 = (uint32_t)__cvta_generic_to_shared(&As[0][wm + 16 + lrow][lsel * 8]);
    uint32_t laB[4];
    #pragma unroll
    for (int p = 0; p < 4; p++)
        laB[p] = (uint32_t)__cvta_generic_to_shared(&Bs[0][lrow][wn + p * 16 + lsel * 8]);

    float acc[2][8][4];
    #pragma unroll
    for (int i = 0; i < 2; i++)
        #pragma unroll
        for (int j = 0; j < 8; j++)
            #pragma unroll
            for (int q = 0; q < 4; q++) acc[i][j][q] = 0.f;

    const int ktiles = Kdim >> 5;
    // prologue: tile 0 -> stage 0
    cp16(sA[0], Ap);           cp16(sA[0] + 16, Ap + 8);
    cp16(sB[0], Bp);           cp16(sB[0] + 16, Bp + 8);
    cp_commit();

    for (int kt = 0; kt < ktiles; kt++) {
        cp_wait0();
        __syncthreads();     // tile kt visible; all warps done computing tile kt-1

        if (kt + 1 < ktiles) {
            const int nb = (kt + 1) & 1;
            const bf16* Ap2 = Ap + (kt + 1) * 32;
            const bf16* Bp2 = Bp + (size_t)(kt + 1) * 32 * Ndim;
            cp16(sA[nb], Ap2);      cp16(sA[nb] + 16, Ap2 + 8);
            cp16(sB[nb], Bp2);      cp16(sB[nb] + 16, Bp2 + 8);
            cp_commit();
        }

        const int s = kt & 1;
        const uint32_t offA = s * A_STAGE, offB = s * B_STAGE;
        #pragma unroll
        for (int ks = 0; ks < 2; ks++) {
            uint32_t a0[4], a1[4], bfr[8][2];
            ldm_x4(a0[0], a0[1], a0[2], a0[3], laA0 + offA + ks * 32);
            ldm_x4(a1[0], a1[1], a1[2], a1[3], laA1 + offA + ks * 32);
            #pragma unroll
            for (int p = 0; p < 4; p++)
                ldm_x4t(bfr[2 * p][0], bfr[2 * p][1], bfr[2 * p + 1][0], bfr[2 * p + 1][1],
                        laB[p] + offB + ks * 16 * (BSTRIDE * 2));
            #pragma unroll
            for (int ni = 0; ni < 8; ni++) {
                mma_bf16(acc[0][ni], a0, bfr[ni]);
                mma_bf16(acc[1][ni], a1, bfr[ni]);
            }
        }
    }

    #pragma unroll
    for (int mi = 0; mi < 2; mi++) {
        int r0 = brow + wm + mi * 16 + lr;
        int r1 = r0 + 8;
        int t0 = (EPI == 1) ? map_token(r0) : r0;
        int t1 = (EPI == 1) ? map_token(r1) : r1;
        #pragma unroll
        for (int ni = 0; ni < 8; ni++) {
            int col = bcol + wn + ni * 8 + 2 * lk;
            float2 bs = *(const float2*)(bias + col);
            float v0 = acc[mi][ni][0] + bs.x, v1 = acc[mi][ni][1] + bs.y;
            float v2 = acc[mi][ni][2] + bs.x, v3 = acc[mi][ni][3] + bs.y;
            if (EPI == 0) {
                *(float2*)(Cout + (size_t)r0 * Ndim + col) = make_float2(v0, v1);
                *(float2*)(Cout + (size_t)r1 * Ndim + col) = make_float2(v2, v3);
            } else if (EPI == 1) {
                float2 e0 = *(const float2*)(extra + (size_t)t0 * CH + col);
                float2 e1 = *(const float2*)(extra + (size_t)t1 * CH + col);
                *(float2*)(Cout + (size_t)t0 * CH + col) = make_float2(e0.x + v0, e0.y + v1);
                *(float2*)(Cout + (size_t)t1 * CH + col) = make_float2(e1.x + v2, e1.y + v3);
            } else if (EPI == 2) {
                const float r2i = 0.70710678118654752f;
                v0 = 0.5f * v0 * (1.0f + erff(v0 * r2i));
                v1 = 0.5f * v1 * (1.0f + erff(v1 * r2i));
                v2 = 0.5f * v2 * (1.0f + erff(v2 * r2i));
                v3 = 0.5f * v3 * (1.0f + erff(v3 * r2i));
                bf162* Co = (bf162*)Cout;
                Co[((size_t)r0 * Ndim + col) >> 1] = __floats2bfloat162_rn(v0, v1);
                Co[((size_t)r1 * Ndim + col) >> 1] = __floats2bfloat162_rn(v2, v3);
            } else {
                float2 e0 = *(const float2*)(extra + (size_t)r0 * CH + col);
                float2 e1 = *(const float2*)(extra + (size_t)r1 * CH + col);
                *(float2*)(Cout + (size_t)r0 * CH + col) = make_float2(e0.x + v0, e0.y + v1);
                *(float2*)(Cout + (size_t)r1 * CH + col) = make_float2(e1.x + v2, e1.y + v3);
            }
        }
    }
}

// ---------------- attention (fp32 in, bf16 out) ----------------
__global__ void __launch_bounds__(128) attn_kernel(const float* __restrict__ qkv,
                                                   const float* __restrict__ rel_bias,
                                                   bf16* __restrict__ out) {
    const int blk = blockIdx.x;
    const int w   = blk >> 3;
    const int hh  = blk & 7;
    const int tid = threadIdx.x;

    __shared__ float q[NTOK][HD + 1];
    __shared__ float k[NTOK][HD + 1];
    __shared__ float v[NTOK][HD + 1];
    __shared__ float S[NTOK][NTOK + 3];

    const float scale = 0.17677669529663687f;

    for (int idx = tid; idx < NTOK * 8; idx += 128) {
        int n = idx >> 3, c4 = (idx & 7) << 2;
        size_t base = (size_t)(w * NTOK + n) * (3 * CH) + hh * HD + c4;
        float4 qv = *(const float4*)(qkv + base);
        float4 kv = *(const float4*)(qkv + base + CH);
        float4 vv = *(const float4*)(qkv + base + 2 * CH);
        q[n][c4 + 0] = qv.x * scale; q[n][c4 + 1] = qv.y * scale;
        q[n][c4 + 2] = qv.z * scale; q[n][c4 + 3] = qv.w * scale;
        k[n][c4 + 0] = kv.x; k[n][c4 + 1] = kv.y; k[n][c4 + 2] = kv.z; k[n][c4 + 3] = kv.w;
        v[n][c4 + 0] = vv.x; v[n][c4 + 1] = vv.y; v[n][c4 + 2] = vv.z; v[n][c4 + 3] = vv.w;
    }
    __syncthreads();

    const int widx = w & 63;
    const int wh = widx >> 3, ww = widx & 7;

    for (int idx = tid; idx < NTOK * NTOK; idx += 128) {
        int n = idx / NTOK, m = idx - n * NTOK;
        float s = 0.f;
        #pragma unroll
        for (int d = 0; d < HD; d++) s += q[n][d] * k[m][d];
        int in_ = n / WS, jn = n - in_ * WS;
        int im  = m / WS, jm = m - im * WS;
        s += rel_bias[((im - in_ + 6) * 13 + (jm - jn + 6)) * HEADS + hh];
        int hn = wh * WS + in_, wn = ww * WS + jn;
        int hm = wh * WS + im,  wm = ww * WS + jm;
        int tn = (hn < 49 ? 0 : (hn < 53 ? 1 : 2)) * 3 + (wn < 49 ? 0 : (wn < 53 ? 1 : 2));
        int tm = (hm < 49 ? 0 : (hm < 53 ? 1 : 2)) * 3 + (wm < 49 ? 0 : (wm < 53 ? 1 : 2));
        if (tn != tm) s -= 100.0f;
        S[n][m] = s;
    }
    __syncthreads();

    const int warp = tid >> 5, lane = tid & 31;
    for (int n = warp; n < NTOK; n += 4) {
        float mx = -1e30f;
        for (int m = lane; m < NTOK; m += 32) mx = fmaxf(mx, S[n][m]);
        #pragma unroll
        for (int o = 16; o; o >>= 1) mx = fmaxf(mx, __shfl_xor_sync(0xffffffffu, mx, o));
        float sum = 0.f;
        for (int m = lane; m < NTOK; m += 32) {
            float e = __expf(S[n][m] - mx);
            S[n][m] = e;
            sum += e;
        }
        #pragma unroll
        for (int o = 16; o; o >>= 1) sum += __shfl_xor_sync(0xffffffffu, sum, o);
        float r = 1.0f / sum;
        for (int m = lane; m < NTOK; m += 32) S[n][m] *= r;
    }
    __syncthreads();

    for (int idx = tid; idx < NTOK * HD; idx += 128) {
        int n = idx >> 5, d = idx & 31;
        float o = 0.f;
        #pragma unroll
        for (int m = 0; m < NTOK; m++) o += S[n][m] * v[m][d];
        out[(size_t)(w * NTOK + n) * CH + hh * HD + d] = __float2bfloat16_rn(o);
    }
}

// ---------------- driver ----------------
extern "C" void kernel_launch(void* const* d_in, const int* in_sizes, int n_in,
                              void* d_out, int out_size) {
    const float* x      = (const float*)d_in[0];
    const float* n1g    = (const float*)d_in[1];
    const float* n1b    = (const float*)d_in[2];
    const float* qkv_w  = (const float*)d_in[3];
    const float* qkv_b  = (const float*)d_in[4];
    const float* relb   = (const float*)d_in[5];
    const float* proj_w = (const float*)d_in[6];
    const float* proj_b = (const float*)d_in[7];
    const float* n2g    = (const float*)d_in[8];
    const float* n2b    = (const float*)d_in[9];
    const float* fc1_w  = (const float*)d_in[10];
    const float* fc1_b  = (const float*)d_in[11];
    const float* fc2_w  = (const float*)d_in[12];
    const float* fc2_b  = (const float*)d_in[13];
    float* out = (float*)d_out;

    bf16 *xw, *z, *m1, *wq, *wp, *w1, *w2;
    float *qkv, *y;
    cudaGetSymbolAddress((void**)&xw,  g_xw);
    cudaGetSymbolAddress((void**)&qkv, g_qkv);
    cudaGetSymbolAddress((void**)&y,   g_y);
    cudaGetSymbolAddress((void**)&z,   g_z);
    cudaGetSymbolAddress((void**)&m1,  g_m1);
    cudaGetSymbolAddress((void**)&wq,  g_wq);
    cudaGetSymbolAddress((void**)&wp,  g_wp);
    cudaGetSymbolAddress((void**)&w1,  g_w1);
    cudaGetSymbolAddress((void**)&w2,  g_w2);

    const int MROWS = T_TOK / 128;  // 784

    conv_bf16<<<96,  256>>>(qkv_w,  wq, 256 * 768);
    conv_bf16<<<32,  256>>>(proj_w, wp, 256 * 256);
    conv_bf16<<<128, 256>>>(fc1_w,  w1, 256 * 1024);
    conv_bf16<<<128, 256>>>(fc2_w,  w2, 1024 * 256);

    ln_kernel<0><<<T_TOK / 8, 256>>>(x, n1g, n1b, xw);
    mma_gemm<0><<<dim3(768 / 128, MROWS), 256>>>(xw, wq, qkv_b, qkv, 768, 256, nullptr);
    attn_kernel<<<2048 * HEADS, 128>>>(qkv, relb, xw);
    mma_gemm<1><<<dim3(256 / 128, MROWS), 256>>>(xw, wp, proj_b, y, 256, 256, x);
    ln_kernel<1><<<T_TOK / 8, 256>>>(y, n2g, n2b, z);
    mma_gemm<2><<<dim3(1024 / 128, MROWS), 256>>>(z, w1, fc1_b, (float*)m1, 1024, 256, nullptr);
    mma_gemm<3><<<dim3(256 / 128, MROWS), 256>>>(m1, w2, fc2_b, out, 256, 1024, y);
}

// round 11
// speedup vs baseline: 5.5538x; 1.0299x over previous
#include <cuda_runtime.h>
#include <cuda_bf16.h>
#include <math.h>
#include <stdint.h>

// ---------------- problem constants ----------------
#define BATCH   32
#define IMG_H   56
#define IMG_W   56
#define CH      256
#define WS      7
#define SHIFT_  3
#define HEADS   8
#define HD      32
#define HIDDEN  1024
#define NTOK    49
#define T_TOK   (BATCH*IMG_H*IMG_W)   // 100352

typedef __nv_bfloat16 bf16;
typedef __nv_bfloat162 bf162;

// ---------------- scratch ----------------
__device__ bf16  g_xw [(size_t)T_TOK * CH];        // bf16: LN1 out, then attn out
__device__ bf16  g_qkv[(size_t)T_TOK * 3 * CH];    // bf16 qkv
__device__ float g_y  [(size_t)T_TOK * CH];
__device__ bf16  g_z  [(size_t)T_TOK * CH];
__device__ bf16  g_m1 [(size_t)T_TOK * HIDDEN];
__device__ bf16  g_wq [256 * 768];
__device__ bf16  g_wp [256 * 256];
__device__ bf16  g_w1 [256 * 1024];
__device__ bf16  g_w2 [1024 * 256];

__device__ __forceinline__ int map_token(int r) {
    int w = r / NTOK, n = r - w * NTOK;
    int b = w >> 6, widx = w & 63;
    int wh = widx >> 3, ww = widx & 7;
    int i = n / WS, j = n - i * WS;
    int h = wh * WS + i + SHIFT_;  if (h >= IMG_H) h -= IMG_H;
    int v = ww * WS + j + SHIFT_;  if (v >= IMG_W) v -= IMG_W;
    return (b * IMG_H + h) * IMG_W + v;
}

__device__ __forceinline__ void mma_bf16(float* c, const uint32_t* a, const uint32_t* b) {
    asm volatile(
        "mma.sync.aligned.m16n8k16.row.col.f32.bf16.bf16.f32 "
        "{%0,%1,%2,%3}, {%4,%5,%6,%7}, {%8,%9}, {%0,%1,%2,%3};\n"
        : "+f"(c[0]), "+f"(c[1]), "+f"(c[2]), "+f"(c[3])
        : "r"(a[0]), "r"(a[1]), "r"(a[2]), "r"(a[3]), "r"(b[0]), "r"(b[1]));
}
__device__ __forceinline__ void ldm_x4(uint32_t& r0, uint32_t& r1, uint32_t& r2, uint32_t& r3, uint32_t a) {
    asm volatile("ldmatrix.sync.aligned.m8n8.x4.shared.b16 {%0,%1,%2,%3}, [%4];"
                 : "=r"(r0), "=r"(r1), "=r"(r2), "=r"(r3) : "r"(a));
}
__device__ __forceinline__ void ldm_x4t(uint32_t& r0, uint32_t& r1, uint32_t& r2, uint32_t& r3, uint32_t a) {
    asm volatile("ldmatrix.sync.aligned.m8n8.x4.trans.shared.b16 {%0,%1,%2,%3}, [%4];"
                 : "=r"(r0), "=r"(r1), "=r"(r2), "=r"(r3) : "r"(a));
}
__device__ __forceinline__ void cp16(uint32_t smem_addr, const void* gptr) {
    asm volatile("cp.async.cg.shared.global [%0], [%1], 16;\n" :: "r"(smem_addr), "l"(gptr));
}
__device__ __forceinline__ void cp_commit() { asm volatile("cp.async.commit_group;\n"); }
__device__ __forceinline__ void cp_wait0()  { asm volatile("cp.async.wait_group 0;\n"); }
__device__ __forceinline__ void cp_wait1()  { asm volatile("cp.async.wait_group 1;\n"); }

// ---------------- fused weight conversion fp32 -> bf16 (one launch) ----------------
#define NW0 (256*768)
#define NW1 (256*256)
#define NW2 (256*1024)
#define NW3 (1024*256)
__global__ void __launch_bounds__(256) conv_all(const float* __restrict__ i0, const float* __restrict__ i1,
                                                const float* __restrict__ i2, const float* __restrict__ i3,
                                                bf16* __restrict__ o0, bf16* __restrict__ o1,
                                                bf16* __restrict__ o2, bf16* __restrict__ o3) {
    int i = (blockIdx.x * blockDim.x + threadIdx.x) * 2;
    const float* in; bf16* out; int off;
    if (i < NW0)                       { in = i0; out = o0; off = i; }
    else if (i < NW0 + NW1)            { in = i1; out = o1; off = i - NW0; }
    else if (i < NW0 + NW1 + NW2)      { in = i2; out = o2; off = i - NW0 - NW1; }
    else if (i < NW0 + NW1 + NW2 + NW3){ in = i3; out = o3; off = i - NW0 - NW1 - NW2; }
    else return;
    float2 f = *(const float2*)(in + off);
    *(bf162*)(out + off) = __floats2bfloat162_rn(f.x, f.y);
}

// ---------------- LayerNorm -> bf16 ----------------
template<int MODE>
__global__ void __launch_bounds__(256) ln_kernel(const float* __restrict__ in,
                                                 const float* __restrict__ gam,
                                                 const float* __restrict__ bet,
                                                 bf16* __restrict__ out) {
    int warp = (blockIdx.x * blockDim.x + threadIdx.x) >> 5;
    int lane = threadIdx.x & 31;
    if (warp >= T_TOK) return;
    int src = (MODE == 0) ? map_token(warp) : warp;

    const float4* row = (const float4*)(in + (size_t)src * CH);
    float4 a = row[lane];
    float4 b = row[lane + 32];

    float s = a.x + a.y + a.z + a.w + b.x + b.y + b.z + b.w;
    #pragma unroll
    for (int o = 16; o; o >>= 1) s += __shfl_xor_sync(0xffffffffu, s, o);
    float mu = s * (1.0f / CH);

    float vs = 0.f, d;
    d = a.x - mu; vs += d * d;  d = a.y - mu; vs += d * d;
    d = a.z - mu; vs += d * d;  d = a.w - mu; vs += d * d;
    d = b.x - mu; vs += d * d;  d = b.y - mu; vs += d * d;
    d = b.z - mu; vs += d * d;  d = b.w - mu; vs += d * d;
    #pragma unroll
    for (int o = 16; o; o >>= 1) vs += __shfl_xor_sync(0xffffffffu, vs, o);
    float inv = rsqrtf(vs * (1.0f / CH) + 1e-5f);

    float4 g0 = ((const float4*)gam)[lane], g1 = ((const float4*)gam)[lane + 32];
    float4 b0 = ((const float4*)bet)[lane], b1 = ((const float4*)bet)[lane + 32];

    bf162* orow = (bf162*)(out + (size_t)warp * CH);
    orow[2 * lane]          = __floats2bfloat162_rn((a.x - mu) * inv * g0.x + b0.x, (a.y - mu) * inv * g0.y + b0.y);
    orow[2 * lane + 1]      = __floats2bfloat162_rn((a.z - mu) * inv * g0.z + b0.z, (a.w - mu) * inv * g0.w + b0.w);
    orow[64 + 2 * lane]     = __floats2bfloat162_rn((b.x - mu) * inv * g1.x + b1.x, (b.y - mu) * inv * g1.y + b1.y);
    orow[64 + 2 * lane + 1] = __floats2bfloat162_rn((b.z - mu) * inv * g1.z + b1.z, (b.w - mu) * inv * g1.w + b1.w);
}

// ---------------- bf16 GEMM 128x128x32, 3-stage cp.async pipeline ----------------
//   EPI 0: +bias -> bf16                       (qkv)
//   EPI 1: scatter map_token, +x +bias -> fp32 (proj+reverse+shortcut)
//   EPI 2: gelu(+bias) -> bf16                 (fc1)
//   EPI 3: +extra +bias -> fp32                (fc2+residual)
#define ASTRIDE 40
#define BSTRIDE 136
#define A_STAGE_B (128 * ASTRIDE * 2)   // 10240 bytes
#define B_STAGE_B (32 * BSTRIDE * 2)    // 8704 bytes
#define SMEM_GEMM (3 * (A_STAGE_B + B_STAGE_B))   // 56832

template<int EPI>
__global__ void __launch_bounds__(256, 2) mma_gemm(const bf16* __restrict__ A,
                                                   const bf16* __restrict__ Bw,
                                                   const float* __restrict__ bias,
                                                   float* __restrict__ Cout,
                                                   int Ndim, int Kdim,
                                                   const float* __restrict__ extra) {
    extern __shared__ char smem[];
    bf16* As = (bf16*)smem;                       // [3][128][ASTRIDE]
    bf16* Bs = (bf16*)(smem + 3 * A_STAGE_B);     // [3][32][BSTRIDE]

    const int tid  = threadIdx.x;
    const int brow = blockIdx.y * 128;
    const int bcol = blockIdx.x * 128;
    const int warp = tid >> 5, lane = tid & 31;
    const int wm = (warp & 3) * 32, wn = (warp >> 2) * 64;
    const int lk = lane & 3, lr = lane >> 2;

    const int ar = tid >> 1, ac = (tid & 1) * 16;
    const int bk = tid >> 3, bc = (tid & 7) * 16;
    const bf16* Ap = A  + (size_t)(brow + ar) * Kdim + ac;
    const bf16* Bp = Bw + (size_t)bk * Ndim + bcol + bc;

    const uint32_t sAb = (uint32_t)__cvta_generic_to_shared(As + ar * ASTRIDE + ac);
    const uint32_t sBb = (uint32_t)__cvta_generic_to_shared(Bs + bk * BSTRIDE + bc);

    const int lrow = lane & 15, lsel = lane >> 4;
    const uint32_t laA0 = (uint32_t)__cvta_generic_to_shared(As + (wm + lrow) * ASTRIDE + lsel * 8);
    const uint32_t laA1 = (uint32_t)__cvta_generic_to_shared(As + (wm + 16 + lrow) * ASTRIDE + lsel * 8);
    uint32_t laB[4];
    #pragma unroll
    for (int p = 0; p < 4; p++)
        laB[p] = (uint32_t)__cvta_generic_to_shared(Bs + lrow * BSTRIDE + wn + p * 16 + lsel * 8);

    float acc[2][8][4];
    #pragma unroll
    for (int i = 0; i < 2; i++)
        #pragma unroll
        for (int j = 0; j < 8; j++)
            #pragma unroll
            for (int q = 0; q < 4; q++) acc[i][j][q] = 0.f;

    const int ktiles = Kdim >> 5;

    // prologue: tiles 0,1 -> stages 0,1
    {
        cp16(sAb, Ap);  cp16(sAb + 16, Ap + 8);
        cp16(sBb, Bp);  cp16(sBb + 16, Bp + 8);
        cp_commit();
        const bf16* Ap2 = Ap + 32;
        const bf16* Bp2 = Bp + (size_t)32 * Ndim;
        cp16(sAb + A_STAGE_B, Ap2);  cp16(sAb + A_STAGE_B + 16, Ap2 + 8);
        cp16(sBb + B_STAGE_B, Bp2);  cp16(sBb + B_STAGE_B + 16, Bp2 + 8);
        cp_commit();
    }

    int cs = 0;
    for (int kt = 0; kt < ktiles; kt++) {
        if (kt + 1 < ktiles) cp_wait1(); else cp_wait0();
        __syncthreads();

        if (kt + 2 < ktiles) {
            int ps = cs + 2; if (ps >= 3) ps -= 3;
            const bf16* Ap2 = Ap + (kt + 2) * 32;
            const bf16* Bp2 = Bp + (size_t)(kt + 2) * 32 * Ndim;
            cp16(sAb + ps * A_STAGE_B, Ap2);  cp16(sAb + ps * A_STAGE_B + 16, Ap2 + 8);
            cp16(sBb + ps * B_STAGE_B, Bp2);  cp16(sBb + ps * B_STAGE_B + 16, Bp2 + 8);
            cp_commit();
        }

        const uint32_t offA = cs * A_STAGE_B, offB = cs * B_STAGE_B;
        #pragma unroll
        for (int ks = 0; ks < 2; ks++) {
            uint32_t a0[4], a1[4], bfr[8][2];
            ldm_x4(a0[0], a0[1], a0[2], a0[3], laA0 + offA + ks * 32);
            ldm_x4(a1[0], a1[1], a1[2], a1[3], laA1 + offA + ks * 32);
            #pragma unroll
            for (int p = 0; p < 4; p++)
                ldm_x4t(bfr[2 * p][0], bfr[2 * p][1], bfr[2 * p + 1][0], bfr[2 * p + 1][1],
                        laB[p] + offB + ks * 16 * (BSTRIDE * 2));
            #pragma unroll
            for (int ni = 0; ni < 8; ni++) {
                mma_bf16(acc[0][ni], a0, bfr[ni]);
                mma_bf16(acc[1][ni], a1, bfr[ni]);
            }
        }
        cs = (cs == 2) ? 0 : cs + 1;
    }

    #pragma unroll
    for (int mi = 0; mi < 2; mi++) {
        int r0 = brow + wm + mi * 16 + lr;
        int r1 = r0 + 8;
        int t0 = (EPI == 1) ? map_token(r0) : r0;
        int t1 = (EPI == 1) ? map_token(r1) : r1;
        #pragma unroll
        for (int ni = 0; ni < 8; ni++) {
            int col = bcol + wn + ni * 8 + 2 * lk;
            float2 bs = *(const float2*)(bias + col);
            float v0 = acc[mi][ni][0] + bs.x, v1 = acc[mi][ni][1] + bs.y;
            float v2 = acc[mi][ni][2] + bs.x, v3 = acc[mi][ni][3] + bs.y;
            if (EPI == 0) {
                bf162* Co = (bf162*)Cout;
                Co[((size_t)r0 * Ndim + col) >> 1] = __floats2bfloat162_rn(v0, v1);
                Co[((size_t)r1 * Ndim + col) >> 1] = __floats2bfloat162_rn(v2, v3);
            } else if (EPI == 1) {
                float2 e0 = *(const float2*)(extra + (size_t)t0 * CH + col);
                float2 e1 = *(const float2*)(extra + (size_t)t1 * CH + col);
                *(float2*)(Cout + (size_t)t0 * CH + col) = make_float2(e0.x + v0, e0.y + v1);
                *(float2*)(Cout + (size_t)t1 * CH + col) = make_float2(e1.x + v2, e1.y + v3);
            } else if (EPI == 2) {
                const float r2i = 0.70710678118654752f;
                v0 = 0.5f * v0 * (1.0f + erff(v0 * r2i));
                v1 = 0.5f * v1 * (1.0f + erff(v1 * r2i));
                v2 = 0.5f * v2 * (1.0f + erff(v2 * r2i));
                v3 = 0.5f * v3 * (1.0f + erff(v3 * r2i));
                bf162* Co = (bf162*)Cout;
                Co[((size_t)r0 * Ndim + col) >> 1] = __floats2bfloat162_rn(v0, v1);
                Co[((size_t)r1 * Ndim + col) >> 1] = __floats2bfloat162_rn(v2, v3);
            } else {
                float2 e0 = *(const float2*)(extra + (size_t)r0 * CH + col);
                float2 e1 = *(const float2*)(extra + (size_t)r1 * CH + col);
                *(float2*)(Cout + (size_t)r0 * CH + col) = make_float2(e0.x + v0, e0.y + v1);
                *(float2*)(Cout + (size_t)r1 * CH + col) = make_float2(e1.x + v2, e1.y + v3);
            }
        }
    }
}

// ---------------- attention (bf16 qkv in, bf16 out) ----------------
__device__ __forceinline__ void unp8(uint4 u, float* dst, float sc) {
    bf162 p;
    p = *(bf162*)&u.x; dst[0] = __low2float(p) * sc; dst[1] = __high2float(p) * sc;
    p = *(bf162*)&u.y; dst[2] = __low2float(p) * sc; dst[3] = __high2float(p) * sc;
    p = *(bf162*)&u.z; dst[4] = __low2float(p) * sc; dst[5] = __high2float(p) * sc;
    p = *(bf162*)&u.w; dst[6] = __low2float(p) * sc; dst[7] = __high2float(p) * sc;
}

__global__ void __launch_bounds__(128) attn_kernel(const bf16* __restrict__ qkv,
                                                   const float* __restrict__ rel_bias,
                                                   bf16* __restrict__ out) {
    const int blk = blockIdx.x;
    const int w   = blk >> 3;
    const int hh  = blk & 7;
    const int tid = threadIdx.x;

    __shared__ float q[NTOK][HD + 1];
    __shared__ float k[NTOK][HD + 1];
    __shared__ float v[NTOK][HD + 1];
    __shared__ float S[NTOK][NTOK + 3];

    const float scale = 0.17677669529663687f;

    for (int idx = tid; idx < NTOK * 4; idx += 128) {
        int n = idx >> 2, c8 = (idx & 3) * 8;
        const bf16* base = qkv + (size_t)(w * NTOK + n) * (3 * CH) + hh * HD + c8;
        uint4 qv = *(const uint4*)(base);
        uint4 kv = *(const uint4*)(base + CH);
        uint4 vv = *(const uint4*)(base + 2 * CH);
        unp8(qv, &q[n][c8], scale);
        unp8(kv, &k[n][c8], 1.0f);
        unp8(vv, &v[n][c8], 1.0f);
    }
    __syncthreads();

    const int widx = w & 63;
    const int wh = widx >> 3, ww = widx & 7;

    for (int idx = tid; idx < NTOK * NTOK; idx += 128) {
        int n = idx / NTOK, m = idx - n * NTOK;
        float s = 0.f;
        #pragma unroll
        for (int d = 0; d < HD; d++) s += q[n][d] * k[m][d];
        int in_ = n / WS, jn = n - in_ * WS;
        int im  = m / WS, jm = m - im * WS;
        s += rel_bias[((im - in_ + 6) * 13 + (jm - jn + 6)) * HEADS + hh];
        int hn = wh * WS + in_, wn = ww * WS + jn;
        int hm = wh * WS + im,  wm = ww * WS + jm;
        int tn = (hn < 49 ? 0 : (hn < 53 ? 1 : 2)) * 3 + (wn < 49 ? 0 : (wn < 53 ? 1 : 2));
        int tm = (hm < 49 ? 0 : (hm < 53 ? 1 : 2)) * 3 + (wm < 49 ? 0 : (wm < 53 ? 1 : 2));
        if (tn != tm) s -= 100.0f;
        S[n][m] = s;
    }
    __syncthreads();

    const int warp = tid >> 5, lane = tid & 31;
    for (int n = warp; n < NTOK; n += 4) {
        float mx = -1e30f;
        for (int m = lane; m < NTOK; m += 32) mx = fmaxf(mx, S[n][m]);
        #pragma unroll
        for (int o = 16; o; o >>= 1) mx = fmaxf(mx, __shfl_xor_sync(0xffffffffu, mx, o));
        float sum = 0.f;
        for (int m = lane; m < NTOK; m += 32) {
            float e = __expf(S[n][m] - mx);
            S[n][m] = e;
            sum += e;
        }
        #pragma unroll
        for (int o = 16; o; o >>= 1) sum += __shfl_xor_sync(0xffffffffu, sum, o);
        float r = 1.0f / sum;
        for (int m = lane; m < NTOK; m += 32) S[n][m] *= r;
    }
    __syncthreads();

    for (int idx = tid; idx < NTOK * HD; idx += 128) {
        int n = idx >> 5, d = idx & 31;
        float o = 0.f;
        #pragma unroll
        for (int m = 0; m < NTOK; m++) o += S[n][m] * v[m][d];
        out[(size_t)(w * NTOK + n) * CH + hh * HD + d] = __float2bfloat16_rn(o);
    }
}

// ---------------- driver ----------------
extern "C" void kernel_launch(void* const* d_in, const int* in_sizes, int n_in,
                              void* d_out, int out_size) {
    const float* x      = (const float*)d_in[0];
    const float* n1g    = (const float*)d_in[1];
    const float* n1b    = (const float*)d_in[2];
    const float* qkv_w  = (const float*)d_in[3];
    const float* qkv_b  = (const float*)d_in[4];
    const float* relb   = (const float*)d_in[5];
    const float* proj_w = (const float*)d_in[6];
    const float* proj_b = (const float*)d_in[7];
    const float* n2g    = (const float*)d_in[8];
    const float* n2b    = (const float*)d_in[9];
    const float* fc1_w  = (const float*)d_in[10];
    const float* fc1_b  = (const float*)d_in[11];
    const float* fc2_w  = (const float*)d_in[12];
    const float* fc2_b  = (const float*)d_in[13];
    float* out = (float*)d_out;

    bf16 *xw, *qkv, *z, *m1, *wq, *wp, *w1, *w2;
    float *y;
    cudaGetSymbolAddress((void**)&xw,  g_xw);
    cudaGetSymbolAddress((void**)&qkv, g_qkv);
    cudaGetSymbolAddress((void**)&y,   g_y);
    cudaGetSymbolAddress((void**)&z,   g_z);
    cudaGetSymbolAddress((void**)&m1,  g_m1);
    cudaGetSymbolAddress((void**)&wq,  g_wq);
    cudaGetSymbolAddress((void**)&wp,  g_wp);
    cudaGetSymbolAddress((void**)&w1,  g_w1);
    cudaGetSymbolAddress((void**)&w2,  g_w2);

    static bool attr_set = false;
    if (!attr_set) {
        cudaFuncSetAttribute(mma_gemm<0>, cudaFuncAttributeMaxDynamicSharedMemorySize, SMEM_GEMM);
        cudaFuncSetAttribute(mma_gemm<1>, cudaFuncAttributeMaxDynamicSharedMemorySize, SMEM_GEMM);
        cudaFuncSetAttribute(mma_gemm<2>, cudaFuncAttributeMaxDynamicSharedMemorySize, SMEM_GEMM);
        cudaFuncSetAttribute(mma_gemm<3>, cudaFuncAttributeMaxDynamicSharedMemorySize, SMEM_GEMM);
        attr_set = true;
    }

    const int MROWS = T_TOK / 128;  // 784

    conv_all<<<(NW0 + NW1 + NW2 + NW3) / 512, 256>>>(qkv_w, proj_w, fc1_w, fc2_w, wq, wp, w1, w2);

    ln_kernel<0><<<T_TOK / 8, 256>>>(x, n1g, n1b, xw);
    mma_gemm<0><<<dim3(768 / 128, MROWS), 256, SMEM_GEMM>>>(xw, wq, qkv_b, (float*)qkv, 768, 256, nullptr);
    attn_kernel<<<2048 * HEADS, 128>>>(qkv, relb, xw);
    mma_gemm<1><<<dim3(256 / 128, MROWS), 256, SMEM_GEMM>>>(xw, wp, proj_b, y, 256, 256, x);
    ln_kernel<1><<<T_TOK / 8, 256>>>(y, n2g, n2b, z);
    mma_gemm<2><<<dim3(1024 / 128, MROWS), 256, SMEM_GEMM>>>(z, w1, fc1_b, (float*)m1, 1024, 256, nullptr);
    mma_gemm<3><<<dim3(256 / 128, MROWS), 256, SMEM_GEMM>>>(m1, w2, fc2_b, out, 256, 1024, y);
}

// round 12
// speedup vs baseline: 5.8630x; 1.0557x over previous
#include <cuda_runtime.h>
#include <cuda_bf16.h>
#include <cuda_fp16.h>
#include <math.h>
#include <stdint.h>

// ---------------- problem constants ----------------
#define BATCH   32
#define IMG_H   56
#define IMG_W   56
#define CH      256
#define WS      7
#define SHIFT_  3
#define HEADS   8
#define HD      32
#define HIDDEN  1024
#define NTOK    49
#define T_TOK   (BATCH*IMG_H*IMG_W)   // 100352

typedef __nv_bfloat16 bf16;
typedef __nv_bfloat162 bf162;

// ---------------- scratch ----------------
__device__ bf16  g_xw [(size_t)T_TOK * CH];
__device__ bf16  g_qkv[(size_t)T_TOK * 3 * CH];
__device__ float g_y  [(size_t)T_TOK * CH];
__device__ bf16  g_z  [(size_t)T_TOK * CH];
__device__ bf16  g_m1 [(size_t)T_TOK * HIDDEN];
__device__ bf16  g_wq [256 * 768];
__device__ bf16  g_wp [256 * 256];
__device__ bf16  g_w1 [256 * 1024];
__device__ bf16  g_w2 [1024 * 256];

__device__ __forceinline__ int map_token(int r) {
    int w = r / NTOK, n = r - w * NTOK;
    int b = w >> 6, widx = w & 63;
    int wh = widx >> 3, ww = widx & 7;
    int i = n / WS, j = n - i * WS;
    int h = wh * WS + i + SHIFT_;  if (h >= IMG_H) h -= IMG_H;
    int v = ww * WS + j + SHIFT_;  if (v >= IMG_W) v -= IMG_W;
    return (b * IMG_H + h) * IMG_W + v;
}

__device__ __forceinline__ void mma_bf16(float* c, const uint32_t* a, const uint32_t* b) {
    asm volatile(
        "mma.sync.aligned.m16n8k16.row.col.f32.bf16.bf16.f32 "
        "{%0,%1,%2,%3}, {%4,%5,%6,%7}, {%8,%9}, {%0,%1,%2,%3};\n"
        : "+f"(c[0]), "+f"(c[1]), "+f"(c[2]), "+f"(c[3])
        : "r"(a[0]), "r"(a[1]), "r"(a[2]), "r"(a[3]), "r"(b[0]), "r"(b[1]));
}
__device__ __forceinline__ void mma_f16(float* c, const uint32_t* a, const uint32_t* b) {
    asm volatile(
        "mma.sync.aligned.m16n8k16.row.col.f32.f16.f16.f32 "
        "{%0,%1,%2,%3}, {%4,%5,%6,%7}, {%8,%9}, {%0,%1,%2,%3};\n"
        : "+f"(c[0]), "+f"(c[1]), "+f"(c[2]), "+f"(c[3])
        : "r"(a[0]), "r"(a[1]), "r"(a[2]), "r"(a[3]), "r"(b[0]), "r"(b[1]));
}
__device__ __forceinline__ void ldm_x4(uint32_t& r0, uint32_t& r1, uint32_t& r2, uint32_t& r3, uint32_t a) {
    asm volatile("ldmatrix.sync.aligned.m8n8.x4.shared.b16 {%0,%1,%2,%3}, [%4];"
                 : "=r"(r0), "=r"(r1), "=r"(r2), "=r"(r3) : "r"(a));
}
__device__ __forceinline__ void ldm_x4t(uint32_t& r0, uint32_t& r1, uint32_t& r2, uint32_t& r3, uint32_t a) {
    asm volatile("ldmatrix.sync.aligned.m8n8.x4.trans.shared.b16 {%0,%1,%2,%3}, [%4];"
                 : "=r"(r0), "=r"(r1), "=r"(r2), "=r"(r3) : "r"(a));
}
__device__ __forceinline__ void cp16(uint32_t smem_addr, const void* gptr) {
    asm volatile("cp.async.cg.shared.global [%0], [%1], 16;\n" :: "r"(smem_addr), "l"(gptr));
}
__device__ __forceinline__ void cp_commit() { asm volatile("cp.async.commit_group;\n"); }
__device__ __forceinline__ void cp_wait0()  { asm volatile("cp.async.wait_group 0;\n"); }
__device__ __forceinline__ void cp_wait1()  { asm volatile("cp.async.wait_group 1;\n"); }

__device__ __forceinline__ uint32_t pack_h2(float x, float y) {
    __half2 h = __float22half2_rn(make_float2(x, y));
    return *(uint32_t*)&h;
}

// ---------------- fused weight conversion ----------------
#define NW0 (256*768)
#define NW1 (256*256)
#define NW2 (256*1024)
#define NW3 (1024*256)
__global__ void __launch_bounds__(256) conv_all(const float* __restrict__ i0, const float* __restrict__ i1,
                                                const float* __restrict__ i2, const float* __restrict__ i3,
                                                bf16* __restrict__ o0, bf16* __restrict__ o1,
                                                bf16* __restrict__ o2, bf16* __restrict__ o3) {
    int i = (blockIdx.x * blockDim.x + threadIdx.x) * 2;
    const float* in; bf16* out; int off;
    if (i < NW0)                       { in = i0; out = o0; off = i; }
    else if (i < NW0 + NW1)            { in = i1; out = o1; off = i - NW0; }
    else if (i < NW0 + NW1 + NW2)      { in = i2; out = o2; off = i - NW0 - NW1; }
    else if (i < NW0 + NW1 + NW2 + NW3){ in = i3; out = o3; off = i - NW0 - NW1 - NW2; }
    else return;
    float2 f = *(const float2*)(in + off);
    *(bf162*)(out + off) = __floats2bfloat162_rn(f.x, f.y);
}

// ---------------- LayerNorm -> bf16 ----------------
template<int MODE>
__global__ void __launch_bounds__(256) ln_kernel(const float* __restrict__ in,
                                                 const float* __restrict__ gam,
                                                 const float* __restrict__ bet,
                                                 bf16* __restrict__ out) {
    int warp = (blockIdx.x * blockDim.x + threadIdx.x) >> 5;
    int lane = threadIdx.x & 31;
    if (warp >= T_TOK) return;
    int src = (MODE == 0) ? map_token(warp) : warp;

    const float4* row = (const float4*)(in + (size_t)src * CH);
    float4 a = row[lane];
    float4 b = row[lane + 32];

    float s = a.x + a.y + a.z + a.w + b.x + b.y + b.z + b.w;
    #pragma unroll
    for (int o = 16; o; o >>= 1) s += __shfl_xor_sync(0xffffffffu, s, o);
    float mu = s * (1.0f / CH);

    float vs = 0.f, d;
    d = a.x - mu; vs += d * d;  d = a.y - mu; vs += d * d;
    d = a.z - mu; vs += d * d;  d = a.w - mu; vs += d * d;
    d = b.x - mu; vs += d * d;  d = b.y - mu; vs += d * d;
    d = b.z - mu; vs += d * d;  d = b.w - mu; vs += d * d;
    #pragma unroll
    for (int o = 16; o; o >>= 1) vs += __shfl_xor_sync(0xffffffffu, vs, o);
    float inv = rsqrtf(vs * (1.0f / CH) + 1e-5f);

    float4 g0 = ((const float4*)gam)[lane], g1 = ((const float4*)gam)[lane + 32];
    float4 b0 = ((const float4*)bet)[lane], b1 = ((const float4*)bet)[lane + 32];

    bf162* orow = (bf162*)(out + (size_t)warp * CH);
    orow[2 * lane]          = __floats2bfloat162_rn((a.x - mu) * inv * g0.x + b0.x, (a.y - mu) * inv * g0.y + b0.y);
    orow[2 * lane + 1]      = __floats2bfloat162_rn((a.z - mu) * inv * g0.z + b0.z, (a.w - mu) * inv * g0.w + b0.w);
    orow[64 + 2 * lane]     = __floats2bfloat162_rn((b.x - mu) * inv * g1.x + b1.x, (b.y - mu) * inv * g1.y + b1.y);
    orow[64 + 2 * lane + 1] = __floats2bfloat162_rn((b.z - mu) * inv * g1.z + b1.z, (b.w - mu) * inv * g1.w + b1.w);
}

// ---------------- bf16 GEMM 128x128x32, 3-stage cp.async ----------------
#define ASTRIDE 40
#define BSTRIDE 136
#define A_STAGE_B (128 * ASTRIDE * 2)
#define B_STAGE_B (32 * BSTRIDE * 2)
#define SMEM_GEMM (3 * (A_STAGE_B + B_STAGE_B))

template<int EPI>
__global__ void __launch_bounds__(256, 2) mma_gemm(const bf16* __restrict__ A,
                                                   const bf16* __restrict__ Bw,
                                                   const float* __restrict__ bias,
                                                   float* __restrict__ Cout,
                                                   int Ndim, int Kdim,
                                                   const float* __restrict__ extra) {
    extern __shared__ char smem[];
    bf16* As = (bf16*)smem;
    bf16* Bs = (bf16*)(smem + 3 * A_STAGE_B);

    const int tid  = threadIdx.x;
    const int brow = blockIdx.y * 128;
    const int bcol = blockIdx.x * 128;
    const int warp = tid >> 5, lane = tid & 31;
    const int wm = (warp & 3) * 32, wn = (warp >> 2) * 64;
    const int lk = lane & 3, lr = lane >> 2;

    const int ar = tid >> 1, ac = (tid & 1) * 16;
    const int bk = tid >> 3, bc = (tid & 7) * 16;
    const bf16* Ap = A  + (size_t)(brow + ar) * Kdim + ac;
    const bf16* Bp = Bw + (size_t)bk * Ndim + bcol + bc;

    const uint32_t sAb = (uint32_t)__cvta_generic_to_shared(As + ar * ASTRIDE + ac);
    const uint32_t sBb = (uint32_t)__cvta_generic_to_shared(Bs + bk * BSTRIDE + bc);

    const int lrow = lane & 15, lsel = lane >> 4;
    const uint32_t laA0 = (uint32_t)__cvta_generic_to_shared(As + (wm + lrow) * ASTRIDE + lsel * 8);
    const uint32_t laA1 = (uint32_t)__cvta_generic_to_shared(As + (wm + 16 + lrow) * ASTRIDE + lsel * 8);
    uint32_t laB[4];
    #pragma unroll
    for (int p = 0; p < 4; p++)
        laB[p] = (uint32_t)__cvta_generic_to_shared(Bs + lrow * BSTRIDE + wn + p * 16 + lsel * 8);

    float acc[2][8][4];
    #pragma unroll
    for (int i = 0; i < 2; i++)
        #pragma unroll
        for (int j = 0; j < 8; j++)
            #pragma unroll
            for (int q = 0; q < 4; q++) acc[i][j][q] = 0.f;

    const int ktiles = Kdim >> 5;
    {
        cp16(sAb, Ap);  cp16(sAb + 16, Ap + 8);
        cp16(sBb, Bp);  cp16(sBb + 16, Bp + 8);
        cp_commit();
        const bf16* Ap2 = Ap + 32;
        const bf16* Bp2 = Bp + (size_t)32 * Ndim;
        cp16(sAb + A_STAGE_B, Ap2);  cp16(sAb + A_STAGE_B + 16, Ap2 + 8);
        cp16(sBb + B_STAGE_B, Bp2);  cp16(sBb + B_STAGE_B + 16, Bp2 + 8);
        cp_commit();
    }

    int cs = 0;
    for (int kt = 0; kt < ktiles; kt++) {
        if (kt + 1 < ktiles) cp_wait1(); else cp_wait0();
        __syncthreads();

        if (kt + 2 < ktiles) {
            int ps = cs + 2; if (ps >= 3) ps -= 3;
            const bf16* Ap2 = Ap + (kt + 2) * 32;
            const bf16* Bp2 = Bp + (size_t)(kt + 2) * 32 * Ndim;
            cp16(sAb + ps * A_STAGE_B, Ap2);  cp16(sAb + ps * A_STAGE_B + 16, Ap2 + 8);
            cp16(sBb + ps * B_STAGE_B, Bp2);  cp16(sBb + ps * B_STAGE_B + 16, Bp2 + 8);
            cp_commit();
        }

        const uint32_t offA = cs * A_STAGE_B, offB = cs * B_STAGE_B;
        #pragma unroll
        for (int ks = 0; ks < 2; ks++) {
            uint32_t a0[4], a1[4], bfr[8][2];
            ldm_x4(a0[0], a0[1], a0[2], a0[3], laA0 + offA + ks * 32);
            ldm_x4(a1[0], a1[1], a1[2], a1[3], laA1 + offA + ks * 32);
            #pragma unroll
            for (int p = 0; p < 4; p++)
                ldm_x4t(bfr[2 * p][0], bfr[2 * p][1], bfr[2 * p + 1][0], bfr[2 * p + 1][1],
                        laB[p] + offB + ks * 16 * (BSTRIDE * 2));
            #pragma unroll
            for (int ni = 0; ni < 8; ni++) {
                mma_bf16(acc[0][ni], a0, bfr[ni]);
                mma_bf16(acc[1][ni], a1, bfr[ni]);
            }
        }
        cs = (cs == 2) ? 0 : cs + 1;
    }

    #pragma unroll
    for (int mi = 0; mi < 2; mi++) {
        int r0 = brow + wm + mi * 16 + lr;
        int r1 = r0 + 8;
        int t0 = (EPI == 1) ? map_token(r0) : r0;
        int t1 = (EPI == 1) ? map_token(r1) : r1;
        #pragma unroll
        for (int ni = 0; ni < 8; ni++) {
            int col = bcol + wn + ni * 8 + 2 * lk;
            float2 bs = *(const float2*)(bias + col);
            float v0 = acc[mi][ni][0] + bs.x, v1 = acc[mi][ni][1] + bs.y;
            float v2 = acc[mi][ni][2] + bs.x, v3 = acc[mi][ni][3] + bs.y;
            if (EPI == 0) {
                bf162* Co = (bf162*)Cout;
                Co[((size_t)r0 * Ndim + col) >> 1] = __floats2bfloat162_rn(v0, v1);
                Co[((size_t)r1 * Ndim + col) >> 1] = __floats2bfloat162_rn(v2, v3);
            } else if (EPI == 1) {
                float2 e0 = *(const float2*)(extra + (size_t)t0 * CH + col);
                float2 e1 = *(const float2*)(extra + (size_t)t1 * CH + col);
                *(float2*)(Cout + (size_t)t0 * CH + col) = make_float2(e0.x + v0, e0.y + v1);
                *(float2*)(Cout + (size_t)t1 * CH + col) = make_float2(e1.x + v2, e1.y + v3);
            } else if (EPI == 2) {
                const float r2i = 0.70710678118654752f;
                v0 = 0.5f * v0 * (1.0f + erff(v0 * r2i));
                v1 = 0.5f * v1 * (1.0f + erff(v1 * r2i));
                v2 = 0.5f * v2 * (1.0f + erff(v2 * r2i));
                v3 = 0.5f * v3 * (1.0f + erff(v3 * r2i));
                bf162* Co = (bf162*)Cout;
                Co[((size_t)r0 * Ndim + col) >> 1] = __floats2bfloat162_rn(v0, v1);
                Co[((size_t)r1 * Ndim + col) >> 1] = __floats2bfloat162_rn(v2, v3);
            } else {
                float2 e0 = *(const float2*)(extra + (size_t)r0 * CH + col);
                float2 e1 = *(const float2*)(extra + (size_t)r1 * CH + col);
                *(float2*)(Cout + (size_t)r0 * CH + col) = make_float2(e0.x + v0, e0.y + v1);
                *(float2*)(Cout + (size_t)r1 * CH + col) = make_float2(e1.x + v2, e1.y + v3);
            }
        }
    }
}

// ---------------- tensor-core attention: one block per (window, head) ----------------
// N=49 padded to 64. Warp w owns M-rows [16w,16w+16). S=QK^T via bf16 MMA,
// softmax in registers, P(fp16)·V(fp16) via MMA with S-frag -> A-frag reuse.
__global__ void __launch_bounds__(128) attn_kernel(const bf16* __restrict__ qkv,
                                                   const float* __restrict__ rel_bias,
                                                   bf16* __restrict__ out) {
    __shared__ bf16   qs[64][40];
    __shared__ bf16   ks[64][40];
    __shared__ __half vs[64][40];
    __shared__ float  sbias[169];
    __shared__ int    sinfo[64];

    const int blk = blockIdx.x;
    const int w = blk >> 3, hh = blk & 7;
    const int tid = threadIdx.x;
    const int warp = tid >> 5, lane = tid & 31;
    const int lr = lane >> 2, lk = lane & 3;
    const int lrow = lane & 15, lsel = lane >> 4;
    const int wm = warp * 16;
    const float scale = 0.17677669529663687f;  // 32^-0.5

    // zero pad rows 49..63 (K: garbage-free S; V: no NaN into PV)
    for (int idx = tid; idx < 15 * 40; idx += 128) {
        int r = 49 + idx / 40, cc = idx - (idx / 40) * 40;
        qs[r][cc] = __float2bfloat16(0.f);
        ks[r][cc] = __float2bfloat16(0.f);
        vs[r][cc] = __float2half(0.f);
    }
    // load head slice: q,k bf16; v -> fp16 (exact)
    for (int idx = tid; idx < 49 * 4; idx += 128) {
        int n = idx >> 2, c8 = (idx & 3) * 8;
        const bf16* base = qkv + (size_t)(w * 49 + n) * (3 * CH) + hh * 32 + c8;
        *(uint4*)&qs[n][c8] = *(const uint4*)(base);
        *(uint4*)&ks[n][c8] = *(const uint4*)(base + CH);
        uint4 vv = *(const uint4*)(base + 2 * CH);
        bf162* vp = (bf162*)&vv;
        __half2 hv[4];
        #pragma unroll
        for (int t = 0; t < 4; t++) hv[t] = __float22half2_rn(__bfloat1622float2(vp[t]));
        *(uint4*)&vs[n][c8] = *(uint4*)hv;
    }
    for (int i = tid; i < 169; i += 128) sbias[i] = rel_bias[i * 8 + hh];
    if (tid < 64) {
        int c = tid, info;
        if (c < 49) {
            int i = (c * 37) >> 8, j = c - 7 * i;
            int wh = (w & 63) >> 3, ww = w & 7;
            int hn = wh * 7 + i, wn = ww * 7 + j;
            int tag = (hn < 49 ? 0 : (hn < 53 ? 1 : 2)) * 3 + (wn < 49 ? 0 : (wn < 53 ? 1 : 2));
            info = (tag << 8) | (i * 13 + j);
        } else info = (15 << 8);
        sinfo[c] = info;
    }
    __syncthreads();

    // ---- S = Q K^T ----
    float c[8][4];
    #pragma unroll
    for (int j = 0; j < 8; j++)
        #pragma unroll
        for (int q = 0; q < 4; q++) c[j][q] = 0.f;

    const uint32_t laQ = (uint32_t)__cvta_generic_to_shared(&qs[wm + lrow][lsel * 8]);
    uint32_t laK[4];
    #pragma unroll
    for (int np = 0; np < 4; np++)
        laK[np] = (uint32_t)__cvta_generic_to_shared(&ks[np * 16 + lrow][lsel * 8]);

    #pragma unroll
    for (int kh = 0; kh < 2; kh++) {
        uint32_t a[4];
        ldm_x4(a[0], a[1], a[2], a[3], laQ + kh * 32);
        #pragma unroll
        for (int np = 0; np < 4; np++) {
            uint32_t r0, r1, r2, r3;
            ldm_x4(r0, r1, r2, r3, laK[np] + kh * 32);
            uint32_t bl[2] = {r0, r2}, bu[2] = {r1, r3};
            mma_bf16(c[2 * np],     a, bl);
            mma_bf16(c[2 * np + 1], a, bu);
        }
    }

    // ---- bias + mask + softmax (rows lr, lr+8 of this warp's tile) ----
    const int ri0 = sinfo[wm + lr], ri1 = sinfo[wm + lr + 8];
    const int rv0 = ri0 & 255, rt0 = ri0 >> 8;
    const int rv1 = ri1 & 255, rt1 = ri1 >> 8;
    float mx0 = -1e30f, mx1 = -1e30f;
    #pragma unroll
    for (int j = 0; j < 8; j++) {
        int ci0 = sinfo[j * 8 + 2 * lk], ci1 = sinfo[j * 8 + 2 * lk + 1];
        int cv0 = ci0 & 255, ct0 = ci0 >> 8;
        int cv1 = ci1 & 255, ct1 = ci1 >> 8;
        c[j][0] = c[j][0] * scale + sbias[cv0 - rv0 + 84] + (ct0 != rt0 ? -100.f : 0.f);
        c[j][1] = c[j][1] * scale + sbias[cv1 - rv0 + 84] + (ct1 != rt0 ? -100.f : 0.f);
        c[j][2] = c[j][2] * scale + sbias[cv0 - rv1 + 84] + (ct0 != rt1 ? -100.f : 0.f);
        c[j][3] = c[j][3] * scale + sbias[cv1 - rv1 + 84] + (ct1 != rt1 ? -100.f : 0.f);
        mx0 = fmaxf(mx0, fmaxf(c[j][0], c[j][1]));
        mx1 = fmaxf(mx1, fmaxf(c[j][2], c[j][3]));
    }
    mx0 = fmaxf(mx0, __shfl_xor_sync(0xffffffffu, mx0, 1));
    mx0 = fmaxf(mx0, __shfl_xor_sync(0xffffffffu, mx0, 2));
    mx1 = fmaxf(mx1, __shfl_xor_sync(0xffffffffu, mx1, 1));
    mx1 = fmaxf(mx1, __shfl_xor_sync(0xffffffffu, mx1, 2));
    float sum0 = 0.f, sum1 = 0.f;
    #pragma unroll
    for (int j = 0; j < 8; j++) {
        c[j][0] = __expf(c[j][0] - mx0);
        c[j][1] = __expf(c[j][1] - mx0);
        c[j][2] = __expf(c[j][2] - mx1);
        c[j][3] = __expf(c[j][3] - mx1);
        sum0 += c[j][0] + c[j][1];
        sum1 += c[j][2] + c[j][3];
    }
    sum0 += __shfl_xor_sync(0xffffffffu, sum0, 1);
    sum0 += __shfl_xor_sync(0xffffffffu, sum0, 2);
    sum1 += __shfl_xor_sync(0xffffffffu, sum1, 1);
    sum1 += __shfl_xor_sync(0xffffffffu, sum1, 2);

    // ---- O = P V  (P fp16 from S-frags, V fp16 trans-ldmatrix) ----
    float co[4][4];
    #pragma unroll
    for (int j = 0; j < 4; j++)
        #pragma unroll
        for (int q = 0; q < 4; q++) co[j][q] = 0.f;

    #pragma unroll
    for (int t = 0; t < 4; t++) {
        uint32_t a[4];
        a[0] = pack_h2(c[2 * t][0],     c[2 * t][1]);
        a[1] = pack_h2(c[2 * t][2],     c[2 * t][3]);
        a[2] = pack_h2(c[2 * t + 1][0], c[2 * t + 1][1]);
        a[3] = pack_h2(c[2 * t + 1][2], c[2 * t + 1][3]);
        #pragma unroll
        for (int p = 0; p < 2; p++) {
            uint32_t r0, r1, r2, r3;
            ldm_x4t(r0, r1, r2, r3,
                    (uint32_t)__cvta_generic_to_shared(&vs[t * 16 + lrow][p * 16 + lsel * 8]));
            uint32_t b0[2] = {r0, r1}, b1[2] = {r2, r3};
            mma_f16(co[2 * p],     a, b0);
            mma_f16(co[2 * p + 1], a, b1);
        }
    }

    const float rinv0 = 1.f / sum0, rinv1 = 1.f / sum1;
    const int row0 = wm + lr, row1 = row0 + 8;
    bf16* ob = out + (size_t)w * 49 * CH + hh * 32;
    #pragma unroll
    for (int nt = 0; nt < 4; nt++) {
        int col = nt * 8 + 2 * lk;
        if (row0 < 49)
            *(bf162*)&ob[(size_t)row0 * CH + col] =
                __floats2bfloat162_rn(co[nt][0] * rinv0, co[nt][1] * rinv0);
        if (row1 < 49)
            *(bf162*)&ob[(size_t)row1 * CH + col] =
                __floats2bfloat162_rn(co[nt][2] * rinv1, co[nt][3] * rinv1);
    }
}

// ---------------- driver ----------------
extern "C" void kernel_launch(void* const* d_in, const int* in_sizes, int n_in,
                              void* d_out, int out_size) {
    const float* x      = (const float*)d_in[0];
    const float* n1g    = (const float*)d_in[1];
    const float* n1b    = (const float*)d_in[2];
    const float* qkv_w  = (const float*)d_in[3];
    const float* qkv_b  = (const float*)d_in[4];
    const float* relb   = (const float*)d_in[5];
    const float* proj_w = (const float*)d_in[6];
    const float* proj_b = (const float*)d_in[7];
    const float* n2g    = (const float*)d_in[8];
    const float* n2b    = (const float*)d_in[9];
    const float* fc1_w  = (const float*)d_in[10];
    const float* fc1_b  = (const float*)d_in[11];
    const float* fc2_w  = (const float*)d_in[12];
    const float* fc2_b  = (const float*)d_in[13];
    float* out = (float*)d_out;

    bf16 *xw, *qkv, *z, *m1, *wq, *wp, *w1, *w2;
    float *y;
    cudaGetSymbolAddress((void**)&xw,  g_xw);
    cudaGetSymbolAddress((void**)&qkv, g_qkv);
    cudaGetSymbolAddress((void**)&y,   g_y);
    cudaGetSymbolAddress((void**)&z,   g_z);
    cudaGetSymbolAddress((void**)&m1,  g_m1);
    cudaGetSymbolAddress((void**)&wq,  g_wq);
    cudaGetSymbolAddress((void**)&wp,  g_wp);
    cudaGetSymbolAddress((void**)&w1,  g_w1);
    cudaGetSymbolAddress((void**)&w2,  g_w2);

    static bool attr_set = false;
    if (!attr_set) {
        cudaFuncSetAttribute(mma_gemm<0>, cudaFuncAttributeMaxDynamicSharedMemorySize, SMEM_GEMM);
        cudaFuncSetAttribute(mma_gemm<1>, cudaFuncAttributeMaxDynamicSharedMemorySize, SMEM_GEMM);
        cudaFuncSetAttribute(mma_gemm<2>, cudaFuncAttributeMaxDynamicSharedMemorySize, SMEM_GEMM);
        cudaFuncSetAttribute(mma_gemm<3>, cudaFuncAttributeMaxDynamicSharedMemorySize, SMEM_GEMM);
        attr_set = true;
    }

    const int MROWS = T_TOK / 128;  // 784

    conv_all<<<(NW0 + NW1 + NW2 + NW3) / 512, 256>>>(qkv_w, proj_w, fc1_w, fc2_w, wq, wp, w1, w2);

    ln_kernel<0><<<T_TOK / 8, 256>>>(x, n1g, n1b, xw);
    mma_gemm<0><<<dim3(768 / 128, MROWS), 256, SMEM_GEMM>>>(xw, wq, qkv_b, (float*)qkv, 768, 256, nullptr);
    attn_kernel<<<2048 * HEADS, 128>>>(qkv, relb, xw);
    mma_gemm<1><<<dim3(256 / 128, MROWS), 256, SMEM_GEMM>>>(xw, wp, proj_b, y, 256, 256, x);
    ln_kernel<1><<<T_TOK / 8, 256>>>(y, n2g, n2b, z);
    mma_gemm<2><<<dim3(1024 / 128, MROWS), 256, SMEM_GEMM>>>(z, w1, fc1_b, (float*)m1, 1024, 256, nullptr);
    mma_gemm<3><<<dim3(256 / 128, MROWS), 256, SMEM_GEMM>>>(m1, w2, fc2_b, out, 256, 1024, y);
}

// round 15
// speedup vs baseline: 6.7961x; 1.1592x over previous
#include <cuda_runtime.h>
#include <cuda_bf16.h>
#include <cuda_fp16.h>
#include <math.h>
#include <stdint.h>

// ---------------- problem constants ----------------
#define BATCH   32
#define IMG_H   56
#define IMG_W   56
#define CH      256
#define WS      7
#define SHIFT_  3
#define HEADS   8
#define HD      32
#define HIDDEN  1024
#define NTOK    49
#define T_TOK   (BATCH*IMG_H*IMG_W)   // 100352

typedef __nv_bfloat16 bf16;
typedef __nv_bfloat162 bf162;

// ---------------- scratch ----------------
__device__ bf16  g_xw [(size_t)T_TOK * CH];
__device__ bf16  g_qkv[(size_t)T_TOK * 3 * CH];
__device__ float g_y  [(size_t)T_TOK * CH];
__device__ bf16  g_z  [(size_t)T_TOK * CH];
__device__ bf16  g_m1 [(size_t)T_TOK * HIDDEN];
__device__ bf16  g_wq [256 * 768];
__device__ bf16  g_wp [256 * 256];
__device__ bf16  g_w1 [256 * 1024];
__device__ bf16  g_w2 [1024 * 256];

__device__ __forceinline__ int map_token(int r) {
    int w = r / NTOK, n = r - w * NTOK;
    int b = w >> 6, widx = w & 63;
    int wh = widx >> 3, ww = widx & 7;
    int i = n / WS, j = n - i * WS;
    int h = wh * WS + i + SHIFT_;  if (h >= IMG_H) h -= IMG_H;
    int v = ww * WS + j + SHIFT_;  if (v >= IMG_W) v -= IMG_W;
    return (b * IMG_H + h) * IMG_W + v;
}

__device__ __forceinline__ void mma_bf16(float* c, const uint32_t* a, const uint32_t* b) {
    asm volatile(
        "mma.sync.aligned.m16n8k16.row.col.f32.bf16.bf16.f32 "
        "{%0,%1,%2,%3}, {%4,%5,%6,%7}, {%8,%9}, {%0,%1,%2,%3};\n"
        : "+f"(c[0]), "+f"(c[1]), "+f"(c[2]), "+f"(c[3])
        : "r"(a[0]), "r"(a[1]), "r"(a[2]), "r"(a[3]), "r"(b[0]), "r"(b[1]));
}
__device__ __forceinline__ void mma_f16(float* c, const uint32_t* a, const uint32_t* b) {
    asm volatile(
        "mma.sync.aligned.m16n8k16.row.col.f32.f16.f16.f32 "
        "{%0,%1,%2,%3}, {%4,%5,%6,%7}, {%8,%9}, {%0,%1,%2,%3};\n"
        : "+f"(c[0]), "+f"(c[1]), "+f"(c[2]), "+f"(c[3])
        : "r"(a[0]), "r"(a[1]), "r"(a[2]), "r"(a[3]), "r"(b[0]), "r"(b[1]));
}
__device__ __forceinline__ void ldm_x4(uint32_t& r0, uint32_t& r1, uint32_t& r2, uint32_t& r3, uint32_t a) {
    asm volatile("ldmatrix.sync.aligned.m8n8.x4.shared.b16 {%0,%1,%2,%3}, [%4];"
                 : "=r"(r0), "=r"(r1), "=r"(r2), "=r"(r3) : "r"(a));
}
__device__ __forceinline__ void ldm_x4t(uint32_t& r0, uint32_t& r1, uint32_t& r2, uint32_t& r3, uint32_t a) {
    asm volatile("ldmatrix.sync.aligned.m8n8.x4.trans.shared.b16 {%0,%1,%2,%3}, [%4];"
                 : "=r"(r0), "=r"(r1), "=r"(r2), "=r"(r3) : "r"(a));
}
__device__ __forceinline__ void cp16(uint32_t smem_addr, const void* gptr) {
    asm volatile("cp.async.cg.shared.global [%0], [%1], 16;\n" :: "r"(smem_addr), "l"(gptr));
}
__device__ __forceinline__ void cp_commit() { asm volatile("cp.async.commit_group;\n"); }
__device__ __forceinline__ void cp_wait0()  { asm volatile("cp.async.wait_group 0;\n"); }
__device__ __forceinline__ void cp_wait1()  { asm volatile("cp.async.wait_group 1;\n"); }

__device__ __forceinline__ uint32_t pack_h2(float x, float y) {
    __half2 h = __float22half2_rn(make_float2(x, y));
    return *(uint32_t*)&h;
}

// ---------------- fused weight conversion ----------------
#define NW0 (256*768)
#define NW1 (256*256)
#define NW2 (256*1024)
#define NW3 (1024*256)
__global__ void __launch_bounds__(256) conv_all(const float* __restrict__ i0, const float* __restrict__ i1,
                                                const float* __restrict__ i2, const float* __restrict__ i3,
                                                bf16* __restrict__ o0, bf16* __restrict__ o1,
                                                bf16* __restrict__ o2, bf16* __restrict__ o3) {
    int i = (blockIdx.x * blockDim.x + threadIdx.x) * 2;
    const float* in; bf16* out; int off;
    if (i < NW0)                       { in = i0; out = o0; off = i; }
    else if (i < NW0 + NW1)            { in = i1; out = o1; off = i - NW0; }
    else if (i < NW0 + NW1 + NW2)      { in = i2; out = o2; off = i - NW0 - NW1; }
    else if (i < NW0 + NW1 + NW2 + NW3){ in = i3; out = o3; off = i - NW0 - NW1 - NW2; }
    else return;
    float2 f = *(const float2*)(in + off);
    *(bf162*)(out + off) = __floats2bfloat162_rn(f.x, f.y);
}

// ---------------- LayerNorm -> bf16 ----------------
template<int MODE>
__global__ void __launch_bounds__(256) ln_kernel(const float* __restrict__ in,
                                                 const float* __restrict__ gam,
                                                 const float* __restrict__ bet,
                                                 bf16* __restrict__ out) {
    int warp = (blockIdx.x * blockDim.x + threadIdx.x) >> 5;
    int lane = threadIdx.x & 31;
    if (warp >= T_TOK) return;
    int src = (MODE == 0) ? map_token(warp) : warp;

    const float4* row = (const float4*)(in + (size_t)src * CH);
    float4 a = row[lane];
    float4 b = row[lane + 32];

    float s = a.x + a.y + a.z + a.w + b.x + b.y + b.z + b.w;
    #pragma unroll
    for (int o = 16; o; o >>= 1) s += __shfl_xor_sync(0xffffffffu, s, o);
    float mu = s * (1.0f / CH);

    float vs = 0.f, d;
    d = a.x - mu; vs += d * d;  d = a.y - mu; vs += d * d;
    d = a.z - mu; vs += d * d;  d = a.w - mu; vs += d * d;
    d = b.x - mu; vs += d * d;  d = b.y - mu; vs += d * d;
    d = b.z - mu; vs += d * d;  d = b.w - mu; vs += d * d;
    #pragma unroll
    for (int o = 16; o; o >>= 1) vs += __shfl_xor_sync(0xffffffffu, vs, o);
    float inv = rsqrtf(vs * (1.0f / CH) + 1e-5f);

    float4 g0 = ((const float4*)gam)[lane], g1 = ((const float4*)gam)[lane + 32];
    float4 b0 = ((const float4*)bet)[lane], b1 = ((const float4*)bet)[lane + 32];

    bf162* orow = (bf162*)(out + (size_t)warp * CH);
    orow[2 * lane]          = __floats2bfloat162_rn((a.x - mu) * inv * g0.x + b0.x, (a.y - mu) * inv * g0.y + b0.y);
    orow[2 * lane + 1]      = __floats2bfloat162_rn((a.z - mu) * inv * g0.z + b0.z, (a.w - mu) * inv * g0.w + b0.w);
    orow[64 + 2 * lane]     = __floats2bfloat162_rn((b.x - mu) * inv * g1.x + b1.x, (b.y - mu) * inv * g1.y + b1.y);
    orow[64 + 2 * lane + 1] = __floats2bfloat162_rn((b.z - mu) * inv * g1.z + b1.z, (b.w - mu) * inv * g1.w + b1.w);
}

// ---------------- bf16 GEMM 256x128x32, 8 warps, warp tile 64x64 ----------------
//   EPI 0: +bias -> bf16      EPI 1: scatter map_token, +x +bias -> fp32
//   EPI 2: gelu(+bias)->bf16  EPI 3: +extra +bias -> fp32
#define ASTRIDE 40
#define BSTRIDE 136
#define A_STAGE_B (256 * ASTRIDE * 2)   // 20480
#define B_STAGE_B (32 * BSTRIDE * 2)    // 8704
#define SMEM_GEMM (3 * (A_STAGE_B + B_STAGE_B))   // 87552

template<int EPI>
__global__ void __launch_bounds__(256) mma_gemm(const bf16* __restrict__ A,
                                                const bf16* __restrict__ Bw,
                                                const float* __restrict__ bias,
                                                float* __restrict__ Cout,
                                                int Ndim, int Kdim,
                                                const float* __restrict__ extra) {
    extern __shared__ char smem[];
    bf16* As = (bf16*)smem;                       // [3][256][ASTRIDE]
    bf16* Bs = (bf16*)(smem + 3 * A_STAGE_B);     // [3][32][BSTRIDE]

    const int tid  = threadIdx.x;
    const int brow = blockIdx.y * 256;
    const int bcol = blockIdx.x * 128;
    const int warp = tid >> 5, lane = tid & 31;
    const int wm = (warp & 3) * 64, wn = (warp >> 2) * 64;
    const int lk = lane & 3, lr = lane >> 2;

    // loaders: A row = tid (4x16B chunks), B row = tid>>3, 2x16B chunks
    const int bk = tid >> 3, bc = (tid & 7) * 16;
    const bf16* Ap = A  + (size_t)(brow + tid) * Kdim;
    const bf16* Bp = Bw + (size_t)bk * Ndim + bcol + bc;

    const uint32_t sAb = (uint32_t)__cvta_generic_to_shared(As + tid * ASTRIDE);
    const uint32_t sBb = (uint32_t)__cvta_generic_to_shared(Bs + bk * BSTRIDE + bc);

    const int lrow = lane & 15, lsel = lane >> 4;
    uint32_t laA[4], laB[4];
    #pragma unroll
    for (int mi = 0; mi < 4; mi++)
        laA[mi] = (uint32_t)__cvta_generic_to_shared(As + (wm + mi * 16 + lrow) * ASTRIDE + lsel * 8);
    #pragma unroll
    for (int p = 0; p < 4; p++)
        laB[p] = (uint32_t)__cvta_generic_to_shared(Bs + lrow * BSTRIDE + wn + p * 16 + lsel * 8);

    float acc[4][8][4];
    #pragma unroll
    for (int i = 0; i < 4; i++)
        #pragma unroll
        for (int j = 0; j < 8; j++)
            #pragma unroll
            for (int q = 0; q < 4; q++) acc[i][j][q] = 0.f;

    const int ktiles = Kdim >> 5;

    // prologue: tiles 0,1 -> stages 0,1
    #pragma unroll
    for (int t = 0; t < 2; t++) {
        const bf16* Ap2 = Ap + t * 32;
        const bf16* Bp2 = Bp + (size_t)t * 32 * Ndim;
        uint32_t aA = sAb + t * A_STAGE_B, aB = sBb + t * B_STAGE_B;
        cp16(aA, Ap2);          cp16(aA + 16, Ap2 + 8);
        cp16(aA + 32, Ap2 + 16); cp16(aA + 48, Ap2 + 24);
        cp16(aB, Bp2);          cp16(aB + 16, Bp2 + 8);
        cp_commit();
    }

    int cs = 0;
    for (int kt = 0; kt < ktiles; kt++) {
        if (kt + 1 < ktiles) cp_wait1(); else cp_wait0();
        __syncthreads();

        if (kt + 2 < ktiles) {
            int ps = cs + 2; if (ps >= 3) ps -= 3;
            const bf16* Ap2 = Ap + (kt + 2) * 32;
            const bf16* Bp2 = Bp + (size_t)(kt + 2) * 32 * Ndim;
            uint32_t aA = sAb + ps * A_STAGE_B, aB = sBb + ps * B_STAGE_B;
            cp16(aA, Ap2);           cp16(aA + 16, Ap2 + 8);
            cp16(aA + 32, Ap2 + 16); cp16(aA + 48, Ap2 + 24);
            cp16(aB, Bp2);           cp16(aB + 16, Bp2 + 8);
            cp_commit();
        }

        const uint32_t offA = cs * A_STAGE_B, offB = cs * B_STAGE_B;
        #pragma unroll
        for (int ks = 0; ks < 2; ks++) {
            uint32_t af[4][4], bfr[8][2];
            #pragma unroll
            for (int mi = 0; mi < 4; mi++)
                ldm_x4(af[mi][0], af[mi][1], af[mi][2], af[mi][3], laA[mi] + offA + ks * 32);
            #pragma unroll
            for (int p = 0; p < 4; p++)
                ldm_x4t(bfr[2 * p][0], bfr[2 * p][1], bfr[2 * p + 1][0], bfr[2 * p + 1][1],
                        laB[p] + offB + ks * 16 * (BSTRIDE * 2));
            #pragma unroll
            for (int mi = 0; mi < 4; mi++)
                #pragma unroll
                for (int ni = 0; ni < 8; ni++)
                    mma_bf16(acc[mi][ni], af[mi], bfr[ni]);
        }
        cs = (cs == 2) ? 0 : cs + 1;
    }

    #pragma unroll
    for (int mi = 0; mi < 4; mi++) {
        int r0 = brow + wm + mi * 16 + lr;
        int r1 = r0 + 8;
        int t0 = (EPI == 1) ? map_token(r0) : r0;
        int t1 = (EPI == 1) ? map_token(r1) : r1;
        #pragma unroll
        for (int ni = 0; ni < 8; ni++) {
            int col = bcol + wn + ni * 8 + 2 * lk;
            float2 bs = *(const float2*)(bias + col);
            float v0 = acc[mi][ni][0] + bs.x, v1 = acc[mi][ni][1] + bs.y;
            float v2 = acc[mi][ni][2] + bs.x, v3 = acc[mi][ni][3] + bs.y;
            if (EPI == 0) {
                bf162* Co = (bf162*)Cout;
                Co[((size_t)r0 * Ndim + col) >> 1] = __floats2bfloat162_rn(v0, v1);
                Co[((size_t)r1 * Ndim + col) >> 1] = __floats2bfloat162_rn(v2, v3);
            } else if (EPI == 1) {
                float2 e0 = *(const float2*)(extra + (size_t)t0 * CH + col);
                float2 e1 = *(const float2*)(extra + (size_t)t1 * CH + col);
                *(float2*)(Cout + (size_t)t0 * CH + col) = make_float2(e0.x + v0, e0.y + v1);
                *(float2*)(Cout + (size_t)t1 * CH + col) = make_float2(e1.x + v2, e1.y + v3);
            } else if (EPI == 2) {
                const float r2i = 0.70710678118654752f;
                v0 = 0.5f * v0 * (1.0f + erff(v0 * r2i));
                v1 = 0.5f * v1 * (1.0f + erff(v1 * r2i));
                v2 = 0.5f * v2 * (1.0f + erff(v2 * r2i));
                v3 = 0.5f * v3 * (1.0f + erff(v3 * r2i));
                bf162* Co = (bf162*)Cout;
                Co[((size_t)r0 * Ndim + col) >> 1] = __floats2bfloat162_rn(v0, v1);
                Co[((size_t)r1 * Ndim + col) >> 1] = __floats2bfloat162_rn(v2, v3);
            } else {
                float2 e0 = *(const float2*)(extra + (size_t)r0 * CH + col);
                float2 e1 = *(const float2*)(extra + (size_t)r1 * CH + col);
                *(float2*)(Cout + (size_t)r0 * CH + col) = make_float2(e0.x + v0, e0.y + v1);
                *(float2*)(Cout + (size_t)r1 * CH + col) = make_float2(e1.x + v2, e1.y + v3);
            }
        }
    }
}

// ---------------- tensor-core attention (R12, unchanged) ----------------
__global__ void __launch_bounds__(128) attn_kernel(const bf16* __restrict__ qkv,
                                                   const float* __restrict__ rel_bias,
                                                   bf16* __restrict__ out) {
    __shared__ bf16   qs[64][40];
    __shared__ bf16   ks[64][40];
    __shared__ __half vs[64][40];
    __shared__ float  sbias[169];
    __shared__ int    sinfo[64];

    const int blk = blockIdx.x;
    const int w = blk >> 3, hh = blk & 7;
    const int tid = threadIdx.x;
    const int warp = tid >> 5, lane = tid & 31;
    const int lr = lane >> 2, lk = lane & 3;
    const int lrow = lane & 15, lsel = lane >> 4;
    const int wm = warp * 16;
    const float scale = 0.17677669529663687f;

    for (int idx = tid; idx < 15 * 40; idx += 128) {
        int r = 49 + idx / 40, cc = idx - (idx / 40) * 40;
        qs[r][cc] = __float2bfloat16(0.f);
        ks[r][cc] = __float2bfloat16(0.f);
        vs[r][cc] = __float2half(0.f);
    }
    for (int idx = tid; idx < 49 * 4; idx += 128) {
        int n = idx >> 2, c8 = (idx & 3) * 8;
        const bf16* base = qkv + (size_t)(w * 49 + n) * (3 * CH) + hh * 32 + c8;
        *(uint4*)&qs[n][c8] = *(const uint4*)(base);
        *(uint4*)&ks[n][c8] = *(const uint4*)(base + CH);
        uint4 vv = *(const uint4*)(base + 2 * CH);
        bf162* vp = (bf162*)&vv;
        __half2 hv[4];
        #pragma unroll
        for (int t = 0; t < 4; t++) hv[t] = __float22half2_rn(__bfloat1622float2(vp[t]));
        *(uint4*)&vs[n][c8] = *(uint4*)hv;
    }
    for (int i = tid; i < 169; i += 128) sbias[i] = rel_bias[i * 8 + hh];
    if (tid < 64) {
        int c = tid, info;
        if (c < 49) {
            int i = (c * 37) >> 8, j = c - 7 * i;
            int wh = (w & 63) >> 3, ww = w & 7;
            int hn = wh * 7 + i, wn = ww * 7 + j;
            int tag = (hn < 49 ? 0 : (hn < 53 ? 1 : 2)) * 3 + (wn < 49 ? 0 : (wn < 53 ? 1 : 2));
            info = (tag << 8) | (i * 13 + j);
        } else info = (15 << 8);
        sinfo[c] = info;
    }
    __syncthreads();

    float c[8][4];
    #pragma unroll
    for (int j = 0; j < 8; j++)
        #pragma unroll
        for (int q = 0; q < 4; q++) c[j][q] = 0.f;

    const uint32_t laQ = (uint32_t)__cvta_generic_to_shared(&qs[wm + lrow][lsel * 8]);
    uint32_t laK[4];
    #pragma unroll
    for (int np = 0; np < 4; np++)
        laK[np] = (uint32_t)__cvta_generic_to_shared(&ks[np * 16 + lrow][lsel * 8]);

    #pragma unroll
    for (int kh = 0; kh < 2; kh++) {
        uint32_t a[4];
        ldm_x4(a[0], a[1], a[2], a[3], laQ + kh * 32);
        #pragma unroll
        for (int np = 0; np < 4; np++) {
            uint32_t r0, r1, r2, r3;
            ldm_x4(r0, r1, r2, r3, laK[np] + kh * 32);
            uint32_t bl[2] = {r0, r2}, bu[2] = {r1, r3};
            mma_bf16(c[2 * np],     a, bl);
            mma_bf16(c[2 * np + 1], a, bu);
        }
    }

    const int ri0 = sinfo[wm + lr], ri1 = sinfo[wm + lr + 8];
    const int rv0 = ri0 & 255, rt0 = ri0 >> 8;
    const int rv1 = ri1 & 255, rt1 = ri1 >> 8;
    float mx0 = -1e30f, mx1 = -1e30f;
    #pragma unroll
    for (int j = 0; j < 8; j++) {
        int ci0 = sinfo[j * 8 + 2 * lk], ci1 = sinfo[j * 8 + 2 * lk + 1];
        int cv0 = ci0 & 255, ct0 = ci0 >> 8;
        int cv1 = ci1 & 255, ct1 = ci1 >> 8;
        c[j][0] = c[j][0] * scale + sbias[cv0 - rv0 + 84] + (ct0 != rt0 ? -100.f : 0.f);
        c[j][1] = c[j][1] * scale + sbias[cv1 - rv0 + 84] + (ct1 != rt0 ? -100.f : 0.f);
        c[j][2] = c[j][2] * scale + sbias[cv0 - rv1 + 84] + (ct0 != rt1 ? -100.f : 0.f);
        c[j][3] = c[j][3] * scale + sbias[cv1 - rv1 + 84] + (ct1 != rt1 ? -100.f : 0.f);
        mx0 = fmaxf(mx0, fmaxf(c[j][0], c[j][1]));
        mx1 = fmaxf(mx1, fmaxf(c[j][2], c[j][3]));
    }
    mx0 = fmaxf(mx0, __shfl_xor_sync(0xffffffffu, mx0, 1));
    mx0 = fmaxf(mx0, __shfl_xor_sync(0xffffffffu, mx0, 2));
    mx1 = fmaxf(mx1, __shfl_xor_sync(0xffffffffu, mx1, 1));
    mx1 = fmaxf(mx1, __shfl_xor_sync(0xffffffffu, mx1, 2));
    float sum0 = 0.f, sum1 = 0.f;
    #pragma unroll
    for (int j = 0; j < 8; j++) {
        c[j][0] = __expf(c[j][0] - mx0);
        c[j][1] = __expf(c[j][1] - mx0);
        c[j][2] = __expf(c[j][2] - mx1);
        c[j][3] = __expf(c[j][3] - mx1);
        sum0 += c[j][0] + c[j][1];
        sum1 += c[j][2] + c[j][3];
    }
    sum0 += __shfl_xor_sync(0xffffffffu, sum0, 1);
    sum0 += __shfl_xor_sync(0xffffffffu, sum0, 2);
    sum1 += __shfl_xor_sync(0xffffffffu, sum1, 1);
    sum1 += __shfl_xor_sync(0xffffffffu, sum1, 2);

    float co[4][4];
    #pragma unroll
    for (int j = 0; j < 4; j++)
        #pragma unroll
        for (int q = 0; q < 4; q++) co[j][q] = 0.f;

    #pragma unroll
    for (int t = 0; t < 4; t++) {
        uint32_t a[4];
        a[0] = pack_h2(c[2 * t][0],     c[2 * t][1]);
        a[1] = pack_h2(c[2 * t][2],     c[2 * t][3]);
        a[2] = pack_h2(c[2 * t + 1][0], c[2 * t + 1][1]);
        a[3] = pack_h2(c[2 * t + 1][2], c[2 * t + 1][3]);
        #pragma unroll
        for (int p = 0; p < 2; p++) {
            uint32_t r0, r1, r2, r3;
            ldm_x4t(r0, r1, r2, r3,
                    (uint32_t)__cvta_generic_to_shared(&vs[t * 16 + lrow][p * 16 + lsel * 8]));
            uint32_t b0[2] = {r0, r1}, b1[2] = {r2, r3};
            mma_f16(co[2 * p],     a, b0);
            mma_f16(co[2 * p + 1], a, b1);
        }
    }

    const float rinv0 = 1.f / sum0, rinv1 = 1.f / sum1;
    const int row0 = wm + lr, row1 = row0 + 8;
    bf16* ob = out + (size_t)w * 49 * CH + hh * 32;
    #pragma unroll
    for (int nt = 0; nt < 4; nt++) {
        int col = nt * 8 + 2 * lk;
        if (row0 < 49)
            *(bf162*)&ob[(size_t)row0 * CH + col] =
                __floats2bfloat162_rn(co[nt][0] * rinv0, co[nt][1] * rinv0);
        if (row1 < 49)
            *(bf162*)&ob[(size_t)row1 * CH + col] =
                __floats2bfloat162_rn(co[nt][2] * rinv1, co[nt][3] * rinv1);
    }
}

// ---------------- driver ----------------
extern "C" void kernel_launch(void* const* d_in, const int* in_sizes, int n_in,
                              void* d_out, int out_size) {
    const float* x      = (const float*)d_in[0];
    const float* n1g    = (const float*)d_in[1];
    const float* n1b    = (const float*)d_in[2];
    const float* qkv_w  = (const float*)d_in[3];
    const float* qkv_b  = (const float*)d_in[4];
    const float* relb   = (const float*)d_in[5];
    const float* proj_w = (const float*)d_in[6];
    const float* proj_b = (const float*)d_in[7];
    const float* n2g    = (const float*)d_in[8];
    const float* n2b    = (const float*)d_in[9];
    const float* fc1_w  = (const float*)d_in[10];
    const float* fc1_b  = (const float*)d_in[11];
    const float* fc2_w  = (const float*)d_in[12];
    const float* fc2_b  = (const float*)d_in[13];
    float* out = (float*)d_out;

    bf16 *xw, *qkv, *z, *m1, *wq, *wp, *w1, *w2;
    float *y;
    cudaGetSymbolAddress((void**)&xw,  g_xw);
    cudaGetSymbolAddress((void**)&qkv, g_qkv);
    cudaGetSymbolAddress((void**)&y,   g_y);
    cudaGetSymbolAddress((void**)&z,   g_z);
    cudaGetSymbolAddress((void**)&m1,  g_m1);
    cudaGetSymbolAddress((void**)&wq,  g_wq);
    cudaGetSymbolAddress((void**)&wp,  g_wp);
    cudaGetSymbolAddress((void**)&w1,  g_w1);
    cudaGetSymbolAddress((void**)&w2,  g_w2);

    static bool attr_set = false;
    if (!attr_set) {
        cudaFuncSetAttribute(mma_gemm<0>, cudaFuncAttributeMaxDynamicSharedMemorySize, SMEM_GEMM);
        cudaFuncSetAttribute(mma_gemm<1>, cudaFuncAttributeMaxDynamicSharedMemorySize, SMEM_GEMM);
        cudaFuncSetAttribute(mma_gemm<2>, cudaFuncAttributeMaxDynamicSharedMemorySize, SMEM_GEMM);
        cudaFuncSetAttribute(mma_gemm<3>, cudaFuncAttributeMaxDynamicSharedMemorySize, SMEM_GEMM);
        attr_set = true;
    }

    const int MROWS = T_TOK / 256;  // 392

    conv_all<<<(NW0 + NW1 + NW2 + NW3) / 512, 256>>>(qkv_w, proj_w, fc1_w, fc2_w, wq, wp, w1, w2);

    ln_kernel<0><<<T_TOK / 8, 256>>>(x, n1g, n1b, xw);
    mma_gemm<0><<<dim3(768 / 128, MROWS), 256, SMEM_GEMM>>>(xw, wq, qkv_b, (float*)qkv, 768, 256, nullptr);
    attn_kernel<<<2048 * HEADS, 128>>>(qkv, relb, xw);
    mma_gemm<1><<<dim3(256 / 128, MROWS), 256, SMEM_GEMM>>>(xw, wp, proj_b, y, 256, 256, x);
    ln_kernel<1><<<T_TOK / 8, 256>>>(y, n2g, n2b, z);
    mma_gemm<2><<<dim3(1024 / 128, MROWS), 256, SMEM_GEMM>>>(z, w1, fc1_b, (float*)m1, 1024, 256, nullptr);
    mma_gemm<3><<<dim3(256 / 128, MROWS), 256, SMEM_GEMM>>>(m1, w2, fc2_b, out, 256, 1024, y);
}